// round 2
// baseline (speedup 1.0000x reference)
#include <cuda_runtime.h>
#include <math.h>

#define NN_MAX 50000
#define DD 128
#define GG 64
#define CC 32
#define EPS 1e-5f

// ---------------- scratch (no allocation allowed) ----------------
__device__ float g_acc[(size_t)NN_MAX * DD];   // self-linear result, then += scatter
__device__ float g_msg[(size_t)NN_MAX * DD];   // message-linear result
__device__ float g_x  [(size_t)NN_MAX * DD];   // activations between layers
__device__ float g_pool[GG * DD];
__device__ float g_cnt [GG];

// ---------------- GEMM: Y[n,128] = X[n,128] @ W[128,128] + bias ----------------
#define BM 64
#define BK 16

__global__ void __launch_bounds__(256) gemm128(const float* __restrict__ X,
                                               const float* __restrict__ W,
                                               const float* __restrict__ B,
                                               float* __restrict__ Y, int nrows)
{
    __shared__ float As[BM][BK];
    __shared__ float Bs[BK][DD];

    const int tid = threadIdx.x;
    const int tx  = tid & 31;   // column group (4 cols each)
    const int ty  = tid >> 5;   // row group (8 rows each)
    const int row0 = blockIdx.x * BM;

    float acc[8][4];
#pragma unroll
    for (int m = 0; m < 8; m++)
#pragma unroll
        for (int n = 0; n < 4; n++) acc[m][n] = 0.f;

    // A-tile load mapping: thread loads one float4
    const int ar = (tid * 4) / BK;
    const int ac = (tid * 4) % BK;
    // B-tile load mapping: thread loads 8 floats (two float4)
    const int br = tid / 16;
    const int bc = (tid % 16) * 8;

    for (int k0 = 0; k0 < DD; k0 += BK) {
        float4 av = make_float4(0.f, 0.f, 0.f, 0.f);
        const int gr = row0 + ar;
        if (gr < nrows)
            av = *reinterpret_cast<const float4*>(&X[(size_t)gr * DD + k0 + ac]);
        *reinterpret_cast<float4*>(&As[ar][ac]) = av;

        float4 b0 = *reinterpret_cast<const float4*>(&W[(size_t)(k0 + br) * DD + bc]);
        float4 b1 = *reinterpret_cast<const float4*>(&W[(size_t)(k0 + br) * DD + bc + 4]);
        *reinterpret_cast<float4*>(&Bs[br][bc])     = b0;
        *reinterpret_cast<float4*>(&Bs[br][bc + 4]) = b1;
        __syncthreads();

#pragma unroll
        for (int kk = 0; kk < BK; kk++) {
            const float4 bv = *reinterpret_cast<const float4*>(&Bs[kk][tx * 4]);
#pragma unroll
            for (int m = 0; m < 8; m++) {
                const float a = As[ty * 8 + m][kk];
                acc[m][0] += a * bv.x;
                acc[m][1] += a * bv.y;
                acc[m][2] += a * bv.z;
                acc[m][3] += a * bv.w;
            }
        }
        __syncthreads();
    }

    const float4 bias = *reinterpret_cast<const float4*>(&B[tx * 4]);
#pragma unroll
    for (int m = 0; m < 8; m++) {
        const int gr = row0 + ty * 8 + m;
        if (gr < nrows) {
            float4 o;
            o.x = acc[m][0] + bias.x;
            o.y = acc[m][1] + bias.y;
            o.z = acc[m][2] + bias.z;
            o.w = acc[m][3] + bias.w;
            *reinterpret_cast<float4*>(&Y[(size_t)gr * DD + tx * 4]) = o;
        }
    }
}

// ---------------- edge scatter: acc[dst] += msg[src] ----------------
#define EPW 4  // edges per warp

__global__ void __launch_bounds__(256) scatter_add(const int* __restrict__ src,
                                                   const int* __restrict__ dst,
                                                   const float* __restrict__ msg,
                                                   float* __restrict__ acc, int nE)
{
    const int lane = threadIdx.x & 31;
    const int warp = (blockIdx.x * blockDim.x + threadIdx.x) >> 5;
    const int e0 = warp * EPW;
#pragma unroll
    for (int i = 0; i < EPW; i++) {
        const int e = e0 + i;
        if (e >= nE) return;
        const int s = __ldg(&src[e]);
        const int d = __ldg(&dst[e]);
        const float4 v = *reinterpret_cast<const float4*>(&msg[(size_t)s * DD + lane * 4]);
        float* p = &acc[(size_t)d * DD + lane * 4];
        asm volatile("red.global.add.v4.f32 [%0], {%1,%2,%3,%4};"
                     :: "l"(p), "f"(v.x), "f"(v.y), "f"(v.z), "f"(v.w) : "memory");
    }
}

// ---------------- fused ReLU + LayerNorm (warp per row) ----------------
__global__ void __launch_bounds__(256) relu_ln(const float* __restrict__ in,
                                               const float* __restrict__ lg,
                                               const float* __restrict__ lb,
                                               float* __restrict__ out, int nrows)
{
    const int lane = threadIdx.x & 31;
    const int row  = (blockIdx.x * blockDim.x + threadIdx.x) >> 5;
    if (row >= nrows) return;

    float4 v = *reinterpret_cast<const float4*>(&in[(size_t)row * DD + lane * 4]);
    v.x = fmaxf(v.x, 0.f); v.y = fmaxf(v.y, 0.f);
    v.z = fmaxf(v.z, 0.f); v.w = fmaxf(v.w, 0.f);

    float s  = v.x + v.y + v.z + v.w;
    float ss = v.x * v.x + v.y * v.y + v.z * v.z + v.w * v.w;
#pragma unroll
    for (int o = 16; o; o >>= 1) {
        s  += __shfl_xor_sync(0xffffffffu, s,  o);
        ss += __shfl_xor_sync(0xffffffffu, ss, o);
    }
    const float mu  = s * (1.f / 128.f);
    const float var = ss * (1.f / 128.f) - mu * mu;
    const float inv = rsqrtf(var + EPS);

    const float4 gv = *reinterpret_cast<const float4*>(&lg[lane * 4]);
    const float4 bv = *reinterpret_cast<const float4*>(&lb[lane * 4]);
    float4 o4;
    o4.x = gv.x * (v.x - mu) * inv + bv.x;
    o4.y = gv.y * (v.y - mu) * inv + bv.y;
    o4.z = gv.z * (v.z - mu) * inv + bv.z;
    o4.w = gv.w * (v.w - mu) * inv + bv.w;
    *reinterpret_cast<float4*>(&out[(size_t)row * DD + lane * 4]) = o4;
}

// ---------------- final layer: ReLU + segment pooling ----------------
__global__ void __launch_bounds__(256) relu_pool(const float* __restrict__ in,
                                                 const int* __restrict__ batch,
                                                 float* __restrict__ pool,
                                                 float* __restrict__ cnt, int nrows)
{
    const int lane = threadIdx.x & 31;
    const int row  = (blockIdx.x * blockDim.x + threadIdx.x) >> 5;
    if (row >= nrows) return;
    const int g = __ldg(&batch[row]);

    float4 v = *reinterpret_cast<const float4*>(&in[(size_t)row * DD + lane * 4]);
    v.x = fmaxf(v.x, 0.f); v.y = fmaxf(v.y, 0.f);
    v.z = fmaxf(v.z, 0.f); v.w = fmaxf(v.w, 0.f);

    float* p = &pool[(size_t)g * DD + lane * 4];
    asm volatile("red.global.add.v4.f32 [%0], {%1,%2,%3,%4};"
                 :: "l"(p), "f"(v.x), "f"(v.y), "f"(v.z), "f"(v.w) : "memory");
    if (lane == 0) atomicAdd(&cnt[g], 1.0f);
}

__global__ void zero_pool(float* pool, float* cnt)
{
    const int t = blockIdx.x * blockDim.x + threadIdx.x;
    if (t < GG * DD) pool[t] = 0.f;
    if (t < GG) cnt[t] = 0.f;
}

// ---------------- head: mean, 2 linears, log_softmax ----------------
__global__ void __launch_bounds__(DD) head_kernel(const float* __restrict__ pool,
                                                  const float* __restrict__ cnt,
                                                  const float* __restrict__ W1,
                                                  const float* __restrict__ b1,
                                                  const float* __restrict__ W2,
                                                  const float* __restrict__ b2,
                                                  float* __restrict__ out)
{
    __shared__ float p[DD];
    __shared__ float h[DD];
    const int g = blockIdx.x;
    const int t = threadIdx.x;

    const float c = fmaxf(cnt[g], 1.f);
    p[t] = pool[g * DD + t] / c;
    __syncthreads();

    float a = b1[t];
#pragma unroll 8
    for (int k = 0; k < DD; k++) a += p[k] * W1[k * DD + t];
    h[t] = a;
    __syncthreads();

    if (t < CC) {
        float l = b2[t];
#pragma unroll 8
        for (int d = 0; d < DD; d++) l += h[d] * W2[d * CC + t];

        float m = l;
#pragma unroll
        for (int o = 16; o; o >>= 1) m = fmaxf(m, __shfl_xor_sync(0xffffffffu, m, o));
        float e = expf(l - m);
        float s = e;
#pragma unroll
        for (int o = 16; o; o >>= 1) s += __shfl_xor_sync(0xffffffffu, s, o);
        out[g * CC + t] = l - m - logf(s);
    }
}

// ---------------- launch ----------------
extern "C" void kernel_launch(void* const* d_in, const int* in_sizes, int n_in,
                              void* d_out, int out_size)
{
    const float* x      = (const float*)d_in[0];
    const float* W_self = (const float*)d_in[1];
    const float* b_self = (const float*)d_in[2];
    const float* W_msg  = (const float*)d_in[3];
    const float* b_msg  = (const float*)d_in[4];
    const float* ln_g   = (const float*)d_in[5];
    const float* ln_b   = (const float*)d_in[6];
    const float* W1     = (const float*)d_in[7];
    const float* b1     = (const float*)d_in[8];
    const float* W2     = (const float*)d_in[9];
    const float* b2     = (const float*)d_in[10];
    const int*   eidx   = (const int*)d_in[11];
    const int*   batch  = (const int*)d_in[12];

    const int nN = in_sizes[0] / DD;
    const int nE = in_sizes[11] / 2;
    const int* src = eidx;
    const int* dst = eidx + nE;

    float *p_acc, *p_msg, *p_x, *p_pool, *p_cnt;
    cudaGetSymbolAddress((void**)&p_acc,  g_acc);
    cudaGetSymbolAddress((void**)&p_msg,  g_msg);
    cudaGetSymbolAddress((void**)&p_x,    g_x);
    cudaGetSymbolAddress((void**)&p_pool, g_pool);
    cudaGetSymbolAddress((void**)&p_cnt,  g_cnt);

    const int gemm_grid    = (nN + BM - 1) / BM;
    const int scatter_grid = (nE + 8 * EPW - 1) / (8 * EPW);   // 8 warps/block
    const int row_grid     = (nN + 7) / 8;                     // 8 rows/block

    zero_pool<<<(GG * DD + 255) / 256, 256>>>(p_pool, p_cnt);

    for (int i = 0; i < 3; i++) {
        const float* xin = (i == 0) ? x : p_x;
        gemm128<<<gemm_grid, 256>>>(xin, W_self + (size_t)i * DD * DD,
                                    b_self + i * DD, p_acc, nN);
        gemm128<<<gemm_grid, 256>>>(xin, W_msg + (size_t)i * DD * DD,
                                    b_msg + i * DD, p_msg, nN);
        scatter_add<<<scatter_grid, 256>>>(src, dst, p_msg, p_acc, nE);
        if (i < 2)
            relu_ln<<<row_grid, 256>>>(p_acc, ln_g + i * DD, ln_b + i * DD, p_x, nN);
    }

    relu_pool<<<row_grid, 256>>>(p_acc, batch, p_pool, p_cnt, nN);
    head_kernel<<<GG, DD>>>(p_pool, p_cnt, W1, b1, W2, b2, (float*)d_out);
}

// round 3
// speedup vs baseline: 1.6175x; 1.6175x over previous
#include <cuda_runtime.h>
#include <math.h>
#include <stdint.h>

#define NN_MAX 50000
#define DD 128
#define GG 64
#define CC 32
#define EPS 1e-5f

// ---------------- scratch (no allocation allowed) ----------------
__device__ float g_acc[(size_t)NN_MAX * DD];
__device__ float g_msg[(size_t)NN_MAX * DD];
__device__ float g_x  [(size_t)NN_MAX * DD];
__device__ float g_pool[GG * DD];
__device__ float g_cnt [GG];
__device__ float g_whi[6 * DD * DD];   // tf32 hi parts of all 6 weight mats
__device__ float g_wlo[6 * DD * DD];   // tf32 lo parts

__device__ __forceinline__ uint32_t f2tf32(float x)
{
    uint32_t r;
    asm("cvt.rna.tf32.f32 %0, %1;" : "=r"(r) : "f"(x));
    return r;
}

__device__ __forceinline__ void mma8(float* c, const uint32_t* a,
                                     uint32_t b0, uint32_t b1)
{
    asm volatile(
        "mma.sync.aligned.m16n8k8.row.col.f32.tf32.tf32.f32 "
        "{%0,%1,%2,%3},{%4,%5,%6,%7},{%8,%9},{%0,%1,%2,%3};"
        : "+f"(c[0]), "+f"(c[1]), "+f"(c[2]), "+f"(c[3])
        : "r"(a[0]), "r"(a[1]), "r"(a[2]), "r"(a[3]), "r"(b0), "r"(b1));
}

// ---------------- weight split: W -> (tf32 hi, tf32 lo) ----------------
__global__ void wsplit(const float* __restrict__ Wself,
                       const float* __restrict__ Wmsg,
                       float* __restrict__ whi, float* __restrict__ wlo)
{
    const int n = 3 * DD * DD;
    int i = blockIdx.x * blockDim.x + threadIdx.x;
    if (i >= 2 * n) return;
    float x = (i < n) ? Wself[i] : Wmsg[i - n];
    uint32_t h = f2tf32(x);
    float hf = __uint_as_float(h);
    uint32_t l = f2tf32(x - hf);
    whi[i] = hf;
    wlo[i] = __uint_as_float(l);
}

// ---------------- tensor-core GEMM: Y = X @ W + bias (tf32 hi/lo comp.) ----------------
__global__ void __launch_bounds__(256) gemm_tc(const float* __restrict__ X,
                                               const float* __restrict__ Wh,
                                               const float* __restrict__ Wl,
                                               const float* __restrict__ Bb,
                                               float* __restrict__ Y, int nrows)
{
    __shared__ float Xs [128][20];   // pad 20: conflict-free A-frag loads
    __shared__ float Whs[16][136];   // pad 136: conflict-free B-frag loads
    __shared__ float Wls[16][136];

    const int tid  = threadIdx.x;
    const int lane = tid & 31;
    const int warp = tid >> 5;
    const int row0 = blockIdx.x * 128;
    const int wr   = warp * 16;        // warp's 16-row slab
    const int gid  = lane >> 2;        // 0..7
    const int tig  = lane & 3;         // 0..3

    float c[16][4];
#pragma unroll
    for (int t = 0; t < 16; t++)
#pragma unroll
        for (int j = 0; j < 4; j++) c[t][j] = 0.f;

    for (int k0 = 0; k0 < DD; k0 += 16) {
        // ---- stage X tile [128 x 16] (coalesced float4) ----
#pragma unroll
        for (int j = 0; j < 2; j++) {
            int fidx = tid * 2 + j;
            int r  = fidx >> 2;
            int cc = (fidx & 3) * 4;
            float4 v = make_float4(0.f, 0.f, 0.f, 0.f);
            int gr = row0 + r;
            if (gr < nrows)
                v = *reinterpret_cast<const float4*>(&X[(size_t)gr * DD + k0 + cc]);
            *reinterpret_cast<float4*>(&Xs[r][cc]) = v;
        }
        // ---- stage W hi/lo tiles [16 x 128] (coalesced float4) ----
#pragma unroll
        for (int j = 0; j < 2; j++) {
            int fidx = tid * 2 + j;
            int k = fidx >> 5;
            int n = (fidx & 31) * 4;
            *reinterpret_cast<float4*>(&Whs[k][n]) =
                *reinterpret_cast<const float4*>(&Wh[(size_t)(k0 + k) * DD + n]);
            *reinterpret_cast<float4*>(&Wls[k][n]) =
                *reinterpret_cast<const float4*>(&Wl[(size_t)(k0 + k) * DD + n]);
        }
        __syncthreads();

#pragma unroll
        for (int kc = 0; kc < 2; kc++) {
            // A fragment (m16k8) + in-register hi/lo split
            uint32_t ah[4], al[4];
#pragma unroll
            for (int i = 0; i < 4; i++) {
                int rr = wr + gid + (i & 1) * 8;
                int cc = kc * 8 + tig + (i >> 1) * 4;
                float a = Xs[rr][cc];
                ah[i] = f2tf32(a);
                al[i] = f2tf32(a - __uint_as_float(ah[i]));
            }
#pragma unroll
            for (int t = 0; t < 16; t++) {
                int n = t * 8 + gid;
                uint32_t bh0 = __float_as_uint(Whs[kc * 8 + tig]    [n]);
                uint32_t bh1 = __float_as_uint(Whs[kc * 8 + tig + 4][n]);
                uint32_t bl0 = __float_as_uint(Wls[kc * 8 + tig]    [n]);
                uint32_t bl1 = __float_as_uint(Wls[kc * 8 + tig + 4][n]);
                mma8(c[t], ah, bh0, bh1);   // hi*hi
                mma8(c[t], ah, bl0, bl1);   // hi*lo
                mma8(c[t], al, bh0, bh1);   // lo*hi
            }
        }
        __syncthreads();
    }

    // ---- epilogue: + bias, store ----
#pragma unroll
    for (int t = 0; t < 16; t++) {
        int col = t * 8 + tig * 2;
        float2 b = *reinterpret_cast<const float2*>(&Bb[col]);
        int r = row0 + wr + gid;
        if (r < nrows) {
            float2 o; o.x = c[t][0] + b.x; o.y = c[t][1] + b.y;
            *reinterpret_cast<float2*>(&Y[(size_t)r * DD + col]) = o;
        }
        int r2 = r + 8;
        if (r2 < nrows) {
            float2 o; o.x = c[t][2] + b.x; o.y = c[t][3] + b.y;
            *reinterpret_cast<float2*>(&Y[(size_t)r2 * DD + col]) = o;
        }
    }
}

// ---------------- edge scatter: acc[dst] += msg[src] ----------------
#define EPW 4

__global__ void __launch_bounds__(256) scatter_add(const int* __restrict__ src,
                                                   const int* __restrict__ dst,
                                                   const float* __restrict__ msg,
                                                   float* __restrict__ acc, int nE)
{
    const int lane = threadIdx.x & 31;
    const int warp = (blockIdx.x * blockDim.x + threadIdx.x) >> 5;
    const int e0 = warp * EPW;
#pragma unroll
    for (int i = 0; i < EPW; i++) {
        const int e = e0 + i;
        if (e >= nE) return;
        const int s = __ldg(&src[e]);
        const int d = __ldg(&dst[e]);
        const float4 v = *reinterpret_cast<const float4*>(&msg[(size_t)s * DD + lane * 4]);
        float* p = &acc[(size_t)d * DD + lane * 4];
        asm volatile("red.global.add.v4.f32 [%0], {%1,%2,%3,%4};"
                     :: "l"(p), "f"(v.x), "f"(v.y), "f"(v.z), "f"(v.w) : "memory");
    }
}

// ---------------- fused ReLU + LayerNorm (warp per row) ----------------
__global__ void __launch_bounds__(256) relu_ln(const float* __restrict__ in,
                                               const float* __restrict__ lg,
                                               const float* __restrict__ lb,
                                               float* __restrict__ out, int nrows)
{
    const int lane = threadIdx.x & 31;
    const int row  = (blockIdx.x * blockDim.x + threadIdx.x) >> 5;
    if (row >= nrows) return;

    float4 v = *reinterpret_cast<const float4*>(&in[(size_t)row * DD + lane * 4]);
    v.x = fmaxf(v.x, 0.f); v.y = fmaxf(v.y, 0.f);
    v.z = fmaxf(v.z, 0.f); v.w = fmaxf(v.w, 0.f);

    float s  = v.x + v.y + v.z + v.w;
    float ss = v.x * v.x + v.y * v.y + v.z * v.z + v.w * v.w;
#pragma unroll
    for (int o = 16; o; o >>= 1) {
        s  += __shfl_xor_sync(0xffffffffu, s,  o);
        ss += __shfl_xor_sync(0xffffffffu, ss, o);
    }
    const float mu  = s * (1.f / 128.f);
    const float var = ss * (1.f / 128.f) - mu * mu;
    const float inv = rsqrtf(var + EPS);

    const float4 gv = *reinterpret_cast<const float4*>(&lg[lane * 4]);
    const float4 bv = *reinterpret_cast<const float4*>(&lb[lane * 4]);
    float4 o4;
    o4.x = gv.x * (v.x - mu) * inv + bv.x;
    o4.y = gv.y * (v.y - mu) * inv + bv.y;
    o4.z = gv.z * (v.z - mu) * inv + bv.z;
    o4.w = gv.w * (v.w - mu) * inv + bv.w;
    *reinterpret_cast<float4*>(&out[(size_t)row * DD + lane * 4]) = o4;
}

// ---------------- final layer: ReLU + segment pooling ----------------
__global__ void __launch_bounds__(256) relu_pool(const float* __restrict__ in,
                                                 const int* __restrict__ batch,
                                                 float* __restrict__ pool,
                                                 float* __restrict__ cnt, int nrows)
{
    const int lane = threadIdx.x & 31;
    const int row  = (blockIdx.x * blockDim.x + threadIdx.x) >> 5;
    if (row >= nrows) return;
    const int g = __ldg(&batch[row]);

    float4 v = *reinterpret_cast<const float4*>(&in[(size_t)row * DD + lane * 4]);
    v.x = fmaxf(v.x, 0.f); v.y = fmaxf(v.y, 0.f);
    v.z = fmaxf(v.z, 0.f); v.w = fmaxf(v.w, 0.f);

    float* p = &pool[(size_t)g * DD + lane * 4];
    asm volatile("red.global.add.v4.f32 [%0], {%1,%2,%3,%4};"
                 :: "l"(p), "f"(v.x), "f"(v.y), "f"(v.z), "f"(v.w) : "memory");
    if (lane == 0) atomicAdd(&cnt[g], 1.0f);
}

__global__ void zero_pool(float* pool, float* cnt)
{
    const int t = blockIdx.x * blockDim.x + threadIdx.x;
    if (t < GG * DD) pool[t] = 0.f;
    if (t < GG) cnt[t] = 0.f;
}

// ---------------- head: mean, 2 linears, log_softmax ----------------
__global__ void __launch_bounds__(DD) head_kernel(const float* __restrict__ pool,
                                                  const float* __restrict__ cnt,
                                                  const float* __restrict__ W1,
                                                  const float* __restrict__ b1,
                                                  const float* __restrict__ W2,
                                                  const float* __restrict__ b2,
                                                  float* __restrict__ out)
{
    __shared__ float p[DD];
    __shared__ float h[DD];
    const int g = blockIdx.x;
    const int t = threadIdx.x;

    const float c = fmaxf(cnt[g], 1.f);
    p[t] = pool[g * DD + t] / c;
    __syncthreads();

    float a = b1[t];
#pragma unroll 8
    for (int k = 0; k < DD; k++) a += p[k] * W1[k * DD + t];
    h[t] = a;
    __syncthreads();

    if (t < CC) {
        float l = b2[t];
#pragma unroll 8
        for (int d = 0; d < DD; d++) l += h[d] * W2[d * CC + t];

        float m = l;
#pragma unroll
        for (int o = 16; o; o >>= 1) m = fmaxf(m, __shfl_xor_sync(0xffffffffu, m, o));
        float e = expf(l - m);
        float s = e;
#pragma unroll
        for (int o = 16; o; o >>= 1) s += __shfl_xor_sync(0xffffffffu, s, o);
        out[g * CC + t] = l - m - logf(s);
    }
}

// ---------------- launch ----------------
extern "C" void kernel_launch(void* const* d_in, const int* in_sizes, int n_in,
                              void* d_out, int out_size)
{
    const float* x      = (const float*)d_in[0];
    const float* W_self = (const float*)d_in[1];
    const float* b_self = (const float*)d_in[2];
    const float* W_msg  = (const float*)d_in[3];
    const float* b_msg  = (const float*)d_in[4];
    const float* ln_g   = (const float*)d_in[5];
    const float* ln_b   = (const float*)d_in[6];
    const float* W1     = (const float*)d_in[7];
    const float* b1     = (const float*)d_in[8];
    const float* W2     = (const float*)d_in[9];
    const float* b2     = (const float*)d_in[10];
    const int*   eidx   = (const int*)d_in[11];
    const int*   batch  = (const int*)d_in[12];

    const int nN = in_sizes[0] / DD;
    const int nE = in_sizes[11] / 2;
    const int* src = eidx;
    const int* dst = eidx + nE;

    float *p_acc, *p_msg, *p_x, *p_pool, *p_cnt, *p_whi, *p_wlo;
    cudaGetSymbolAddress((void**)&p_acc,  g_acc);
    cudaGetSymbolAddress((void**)&p_msg,  g_msg);
    cudaGetSymbolAddress((void**)&p_x,    g_x);
    cudaGetSymbolAddress((void**)&p_pool, g_pool);
    cudaGetSymbolAddress((void**)&p_cnt,  g_cnt);
    cudaGetSymbolAddress((void**)&p_whi,  g_whi);
    cudaGetSymbolAddress((void**)&p_wlo,  g_wlo);

    const int gemm_grid    = (nN + 127) / 128;
    const int scatter_grid = (nE + 8 * EPW - 1) / (8 * EPW);
    const int row_grid     = (nN + 7) / 8;

    wsplit<<<(6 * DD * DD + 255) / 256, 256>>>(W_self, W_msg, p_whi, p_wlo);
    zero_pool<<<(GG * DD + 255) / 256, 256>>>(p_pool, p_cnt);

    for (int i = 0; i < 3; i++) {
        const float* xin = (i == 0) ? x : p_x;
        const float* whS = p_whi + (size_t)i * DD * DD;
        const float* wlS = p_wlo + (size_t)i * DD * DD;
        const float* whM = p_whi + (size_t)(3 + i) * DD * DD;
        const float* wlM = p_wlo + (size_t)(3 + i) * DD * DD;

        gemm_tc<<<gemm_grid, 256>>>(xin, whS, wlS, b_self + i * DD, p_acc, nN);
        gemm_tc<<<gemm_grid, 256>>>(xin, whM, wlM, b_msg + i * DD, p_msg, nN);
        scatter_add<<<scatter_grid, 256>>>(src, dst, p_msg, p_acc, nE);
        if (i < 2)
            relu_ln<<<row_grid, 256>>>(p_acc, ln_g + i * DD, ln_b + i * DD, p_x, nN);
    }

    relu_pool<<<row_grid, 256>>>(p_acc, batch, p_pool, p_cnt, nN);
    head_kernel<<<GG, DD>>>(p_pool, p_cnt, W1, b1, W2, b2, (float*)d_out);
}

// round 6
// speedup vs baseline: 1.8173x; 1.1236x over previous
#include <cuda_runtime.h>
#include <math.h>
#include <stdint.h>

#define NN_MAX 50000
#define NE_MAX 1000000
#define DD 128
#define GG 64
#define CC 32
#define EPS 1e-5f

// ---------------- scratch (no allocation allowed) ----------------
__device__ float g_acc[(size_t)NN_MAX * DD];   // self-linear result
__device__ float g_msg[(size_t)NN_MAX * DD];   // message-linear result
__device__ float g_x  [(size_t)NN_MAX * DD];   // activations between layers
__device__ float g_pool[GG * DD];
__device__ float g_cnt [GG];
__device__ float g_whi[6 * DD * DD];           // tf32 hi of all 6 weight mats
__device__ float g_wlo[6 * DD * DD];           // tf32 lo
__device__ int   g_deg[NN_MAX];                // CSR: per-dst degree
__device__ int   g_off[NN_MAX + 1];            // CSR: row offsets
__device__ int   g_cur[NN_MAX];                // CSR: placement cursors
__device__ int   g_elist[NE_MAX];              // CSR: src list grouped by dst

__device__ __forceinline__ uint32_t f2tf32(float x)
{
    uint32_t r;
    asm("cvt.rna.tf32.f32 %0, %1;" : "=r"(r) : "f"(x));
    return r;
}

__device__ __forceinline__ void mma8(float* c, const uint32_t* a,
                                     uint32_t b0, uint32_t b1)
{
    asm volatile(
        "mma.sync.aligned.m16n8k8.row.col.f32.tf32.tf32.f32 "
        "{%0,%1,%2,%3},{%4,%5,%6,%7},{%8,%9},{%0,%1,%2,%3};"
        : "+f"(c[0]), "+f"(c[1]), "+f"(c[2]), "+f"(c[3])
        : "r"(a[0]), "r"(a[1]), "r"(a[2]), "r"(a[3]), "r"(b0), "r"(b1));
}

// ---------------- weight split: W -> (tf32 hi, tf32 lo) ----------------
__global__ void wsplit(const float* __restrict__ Wself,
                       const float* __restrict__ Wmsg,
                       float* __restrict__ whi, float* __restrict__ wlo)
{
    const int n = 3 * DD * DD;
    int i = blockIdx.x * blockDim.x + threadIdx.x;
    if (i >= 2 * n) return;
    float x = (i < n) ? Wself[i] : Wmsg[i - n];
    uint32_t h = f2tf32(x);
    float hf = __uint_as_float(h);
    uint32_t l = f2tf32(x - hf);
    whi[i] = hf;
    wlo[i] = __uint_as_float(l);
}

// ---------------- CSR build ----------------
__global__ void zero_misc(float* pool, float* cnt, int* deg, int nN)
{
    const int t = blockIdx.x * blockDim.x + threadIdx.x;
    if (t < GG * DD) pool[t] = 0.f;
    if (t < GG) cnt[t] = 0.f;
    if (t < nN) deg[t] = 0;
}

__global__ void csr_hist(const int* __restrict__ dst, int* __restrict__ deg,
                         int nE)
{
    int e = blockIdx.x * blockDim.x + threadIdx.x;
    if (e < nE) atomicAdd(&deg[dst[e]], 1);
}

__global__ void __launch_bounds__(1024) csr_scan(const int* __restrict__ deg,
                                                 int* __restrict__ off,
                                                 int* __restrict__ cur,
                                                 int nN, int nE)
{
    __shared__ int part[1024];
    const int t = threadIdx.x;
    const int chunk = (nN + 1023) >> 10;
    const int b = t * chunk;
    const int e = min(b + chunk, nN);
    int s = 0;
    for (int i = b; i < e; i++) s += deg[i];
    part[t] = s;
    __syncthreads();
#pragma unroll
    for (int o = 1; o < 1024; o <<= 1) {
        int v = (t >= o) ? part[t - o] : 0;
        __syncthreads();
        part[t] += v;
        __syncthreads();
    }
    int run = (t == 0) ? 0 : part[t - 1];
    for (int i = b; i < e; i++) {
        off[i] = run;
        cur[i] = run;
        run += deg[i];
    }
    if (t == 0) off[nN] = nE;
}

__global__ void csr_place(const int* __restrict__ src,
                          const int* __restrict__ dst,
                          int* __restrict__ cur, int* __restrict__ elist, int nE)
{
    int e = blockIdx.x * blockDim.x + threadIdx.x;
    if (e < nE) {
        int p = atomicAdd(&cur[dst[e]], 1);
        elist[p] = src[e];
    }
}

// ---------------- fused dual GEMM (tf32 hi/lo): Ys = X@Ws+bs, Ym = X@Wm+bm ----
// CTA: 64 rows; warps 0-3 -> self, warps 4-7 -> msg (shared X tile)
__global__ void __launch_bounds__(256) gemm_dual(const float* __restrict__ X,
                                                 const float* __restrict__ WsH,
                                                 const float* __restrict__ WsL,
                                                 const float* __restrict__ WmH,
                                                 const float* __restrict__ WmL,
                                                 const float* __restrict__ bS,
                                                 const float* __restrict__ bM,
                                                 float* __restrict__ Ys,
                                                 float* __restrict__ Ym, int nrows)
{
    __shared__ float Xs[64][20];        // pad: conflict-free A-frag loads
    __shared__ float Bs[4][16][136];    // 0=WsH 1=WsL 2=WmH 3=WmL

    const int tid  = threadIdx.x;
    const int lane = tid & 31;
    const int warp = tid >> 5;
    const int half = warp >> 2;         // 0: self, 1: msg
    const int wr   = (warp & 3) * 16;   // 16-row slab within 64
    const int row0 = blockIdx.x * 64;
    const int gid  = lane >> 2;
    const int tig  = lane & 3;

    float c[16][4];
#pragma unroll
    for (int t = 0; t < 16; t++)
#pragma unroll
        for (int j = 0; j < 4; j++) c[t][j] = 0.f;

    for (int k0 = 0; k0 < DD; k0 += 16) {
        // stage X tile [64 x 16]: 256 float4s, one per thread
        {
            int r  = tid >> 2;
            int cc = (tid & 3) * 4;
            float4 v = make_float4(0.f, 0.f, 0.f, 0.f);
            int gr = row0 + r;
            if (gr < nrows)
                v = *reinterpret_cast<const float4*>(&X[(size_t)gr * DD + k0 + cc]);
            *reinterpret_cast<float4*>(&Xs[r][cc]) = v;
        }
        // stage all 4 W tiles [16 x 128]: 4 x 512 float4, 8 per thread
#pragma unroll
        for (int m = 0; m < 4; m++) {
            const float* Wp = (m == 0) ? WsH : (m == 1) ? WsL : (m == 2) ? WmH : WmL;
#pragma unroll
            for (int j = 0; j < 2; j++) {
                int fidx = tid * 2 + j;            // 0..511
                int k = fidx >> 5;
                int n = (fidx & 31) * 4;
                *reinterpret_cast<float4*>(&Bs[m][k][n]) =
                    *reinterpret_cast<const float4*>(&Wp[(size_t)(k0 + k) * DD + n]);
            }
        }
        __syncthreads();

#pragma unroll
        for (int kc = 0; kc < 2; kc++) {
            uint32_t ah[4], al[4];
#pragma unroll
            for (int i = 0; i < 4; i++) {
                int rr = wr + gid + (i & 1) * 8;
                int cc = kc * 8 + tig + (i >> 1) * 4;
                float a = Xs[rr][cc];
                ah[i] = f2tf32(a);
                al[i] = f2tf32(a - __uint_as_float(ah[i]));
            }
            const int hi = half * 2, lo = half * 2 + 1;
#pragma unroll
            for (int t = 0; t < 16; t++) {
                int n = t * 8 + gid;
                uint32_t bh0 = __float_as_uint(Bs[hi][kc * 8 + tig]    [n]);
                uint32_t bh1 = __float_as_uint(Bs[hi][kc * 8 + tig + 4][n]);
                uint32_t bl0 = __float_as_uint(Bs[lo][kc * 8 + tig]    [n]);
                uint32_t bl1 = __float_as_uint(Bs[lo][kc * 8 + tig + 4][n]);
                mma8(c[t], ah, bh0, bh1);   // hi*hi
                mma8(c[t], ah, bl0, bl1);   // hi*lo
                mma8(c[t], al, bh0, bh1);   // lo*hi
            }
        }
        __syncthreads();
    }

    float* Y = half ? Ym : Ys;
    const float* bias = half ? bM : bS;
#pragma unroll
    for (int t = 0; t < 16; t++) {
        int col = t * 8 + tig * 2;
        float2 b = *reinterpret_cast<const float2*>(&bias[col]);
        int r = row0 + wr + gid;
        if (r < nrows) {
            float2 o; o.x = c[t][0] + b.x; o.y = c[t][1] + b.y;
            *reinterpret_cast<float2*>(&Y[(size_t)r * DD + col]) = o;
        }
        int r2 = r + 8;
        if (r2 < nrows) {
            float2 o; o.x = c[t][2] + b.x; o.y = c[t][3] + b.y;
            *reinterpret_cast<float2*>(&Y[(size_t)r2 * DD + col]) = o;
        }
    }
}

// ---------------- gather (CSR) + ReLU + LayerNorm, warp per node ----------------
__global__ void __launch_bounds__(256) gather_ln(const int* __restrict__ off,
                                                 const int* __restrict__ elist,
                                                 const float* __restrict__ msg,
                                                 const float* __restrict__ selfv,
                                                 const float* __restrict__ lg,
                                                 const float* __restrict__ lb,
                                                 float* __restrict__ out, int nN)
{
    const int lane = threadIdx.x & 31;
    const int row  = (blockIdx.x * blockDim.x + threadIdx.x) >> 5;
    if (row >= nN) return;

    float4 a0 = *reinterpret_cast<const float4*>(&selfv[(size_t)row * DD + lane * 4]);
    float4 a1 = make_float4(0.f, 0.f, 0.f, 0.f);

    const int b = __ldg(&off[row]);
    const int e = __ldg(&off[row + 1]);
    int i = b;
    for (; i + 2 <= e; i += 2) {
        int s0 = __ldg(&elist[i]);
        int s1 = __ldg(&elist[i + 1]);
        float4 v0 = *reinterpret_cast<const float4*>(&msg[(size_t)s0 * DD + lane * 4]);
        float4 v1 = *reinterpret_cast<const float4*>(&msg[(size_t)s1 * DD + lane * 4]);
        a0.x += v0.x; a0.y += v0.y; a0.z += v0.z; a0.w += v0.w;
        a1.x += v1.x; a1.y += v1.y; a1.z += v1.z; a1.w += v1.w;
    }
    if (i < e) {
        int s0 = __ldg(&elist[i]);
        float4 v0 = *reinterpret_cast<const float4*>(&msg[(size_t)s0 * DD + lane * 4]);
        a0.x += v0.x; a0.y += v0.y; a0.z += v0.z; a0.w += v0.w;
    }
    float4 v;
    v.x = fmaxf(a0.x + a1.x, 0.f);
    v.y = fmaxf(a0.y + a1.y, 0.f);
    v.z = fmaxf(a0.z + a1.z, 0.f);
    v.w = fmaxf(a0.w + a1.w, 0.f);

    float s  = v.x + v.y + v.z + v.w;
    float ss = v.x * v.x + v.y * v.y + v.z * v.z + v.w * v.w;
#pragma unroll
    for (int o = 16; o; o >>= 1) {
        s  += __shfl_xor_sync(0xffffffffu, s,  o);
        ss += __shfl_xor_sync(0xffffffffu, ss, o);
    }
    const float mu  = s * (1.f / 128.f);
    const float var = ss * (1.f / 128.f) - mu * mu;
    const float inv = rsqrtf(var + EPS);

    const float4 gv = *reinterpret_cast<const float4*>(&lg[lane * 4]);
    const float4 bv = *reinterpret_cast<const float4*>(&lb[lane * 4]);
    float4 o4;
    o4.x = gv.x * (v.x - mu) * inv + bv.x;
    o4.y = gv.y * (v.y - mu) * inv + bv.y;
    o4.z = gv.z * (v.z - mu) * inv + bv.z;
    o4.w = gv.w * (v.w - mu) * inv + bv.w;
    *reinterpret_cast<float4*>(&out[(size_t)row * DD + lane * 4]) = o4;
}

// ---------------- gather (CSR) + ReLU + pool, warp per node ----------------
__global__ void __launch_bounds__(256) gather_pool(const int* __restrict__ off,
                                                   const int* __restrict__ elist,
                                                   const float* __restrict__ msg,
                                                   const float* __restrict__ selfv,
                                                   const int* __restrict__ batch,
                                                   float* __restrict__ pool,
                                                   float* __restrict__ cnt, int nN)
{
    const int lane = threadIdx.x & 31;
    const int row  = (blockIdx.x * blockDim.x + threadIdx.x) >> 5;
    if (row >= nN) return;

    float4 a0 = *reinterpret_cast<const float4*>(&selfv[(size_t)row * DD + lane * 4]);
    float4 a1 = make_float4(0.f, 0.f, 0.f, 0.f);

    const int b = __ldg(&off[row]);
    const int e = __ldg(&off[row + 1]);
    int i = b;
    for (; i + 2 <= e; i += 2) {
        int s0 = __ldg(&elist[i]);
        int s1 = __ldg(&elist[i + 1]);
        float4 v0 = *reinterpret_cast<const float4*>(&msg[(size_t)s0 * DD + lane * 4]);
        float4 v1 = *reinterpret_cast<const float4*>(&msg[(size_t)s1 * DD + lane * 4]);
        a0.x += v0.x; a0.y += v0.y; a0.z += v0.z; a0.w += v0.w;
        a1.x += v1.x; a1.y += v1.y; a1.z += v1.z; a1.w += v1.w;
    }
    if (i < e) {
        int s0 = __ldg(&elist[i]);
        float4 v0 = *reinterpret_cast<const float4*>(&msg[(size_t)s0 * DD + lane * 4]);
        a0.x += v0.x; a0.y += v0.y; a0.z += v0.z; a0.w += v0.w;
    }
    float4 v;
    v.x = fmaxf(a0.x + a1.x, 0.f);
    v.y = fmaxf(a0.y + a1.y, 0.f);
    v.z = fmaxf(a0.z + a1.z, 0.f);
    v.w = fmaxf(a0.w + a1.w, 0.f);

    const int g = __ldg(&batch[row]);
    float* p = &pool[(size_t)g * DD + lane * 4];
    asm volatile("red.global.add.v4.f32 [%0], {%1,%2,%3,%4};"
                 :: "l"(p), "f"(v.x), "f"(v.y), "f"(v.z), "f"(v.w) : "memory");
    if (lane == 0) atomicAdd(&cnt[g], 1.0f);
}

// ---------------- head: mean, 2 linears, log_softmax ----------------
__global__ void __launch_bounds__(DD) head_kernel(const float* __restrict__ pool,
                                                  const float* __restrict__ cnt,
                                                  const float* __restrict__ W1,
                                                  const float* __restrict__ b1,
                                                  const float* __restrict__ W2,
                                                  const float* __restrict__ b2,
                                                  float* __restrict__ out)
{
    __shared__ float p[DD];
    __shared__ float h[DD];
    const int g = blockIdx.x;
    const int t = threadIdx.x;

    const float c = fmaxf(cnt[g], 1.f);
    p[t] = pool[g * DD + t] / c;
    __syncthreads();

    float a = b1[t];
#pragma unroll 8
    for (int k = 0; k < DD; k++) a += p[k] * W1[k * DD + t];
    h[t] = a;
    __syncthreads();

    if (t < CC) {
        float l = b2[t];
#pragma unroll 8
        for (int d = 0; d < DD; d++) l += h[d] * W2[d * CC + t];

        float m = l;
#pragma unroll
        for (int o = 16; o; o >>= 1) m = fmaxf(m, __shfl_xor_sync(0xffffffffu, m, o));
        float e = expf(l - m);
        float s = e;
#pragma unroll
        for (int o = 16; o; o >>= 1) s += __shfl_xor_sync(0xffffffffu, s, o);
        out[g * CC + t] = l - m - logf(s);
    }
}

// ---------------- launch ----------------
extern "C" void kernel_launch(void* const* d_in, const int* in_sizes, int n_in,
                              void* d_out, int out_size)
{
    const float* x      = (const float*)d_in[0];
    const float* W_self = (const float*)d_in[1];
    const float* b_self = (const float*)d_in[2];
    const float* W_msg  = (const float*)d_in[3];
    const float* b_msg  = (const float*)d_in[4];
    const float* ln_g   = (const float*)d_in[5];
    const float* ln_b   = (const float*)d_in[6];
    const float* W1     = (const float*)d_in[7];
    const float* b1     = (const float*)d_in[8];
    const float* W2     = (const float*)d_in[9];
    const float* b2     = (const float*)d_in[10];
    const int*   eidx   = (const int*)d_in[11];
    const int*   batch  = (const int*)d_in[12];

    const int nN = in_sizes[0] / DD;
    const int nE = in_sizes[11] / 2;
    const int* src = eidx;
    const int* dst = eidx + nE;

    float *p_acc, *p_msg, *p_x, *p_pool, *p_cnt, *p_whi, *p_wlo;
    int *p_deg, *p_off, *p_cur, *p_elist;
    cudaGetSymbolAddress((void**)&p_acc,   g_acc);
    cudaGetSymbolAddress((void**)&p_msg,   g_msg);
    cudaGetSymbolAddress((void**)&p_x,     g_x);
    cudaGetSymbolAddress((void**)&p_pool,  g_pool);
    cudaGetSymbolAddress((void**)&p_cnt,   g_cnt);
    cudaGetSymbolAddress((void**)&p_whi,   g_whi);
    cudaGetSymbolAddress((void**)&p_wlo,   g_wlo);
    cudaGetSymbolAddress((void**)&p_deg,   g_deg);
    cudaGetSymbolAddress((void**)&p_off,   g_off);
    cudaGetSymbolAddress((void**)&p_cur,   g_cur);
    cudaGetSymbolAddress((void**)&p_elist, g_elist);

    const int gemm_grid = (nN + 63) / 64;
    const int row_grid  = (nN + 7) / 8;
    const int e_grid    = (nE + 255) / 256;

    wsplit<<<(6 * DD * DD + 255) / 256, 256>>>(W_self, W_msg, p_whi, p_wlo);
    zero_misc<<<(nN + 255) / 256, 256>>>(p_pool, p_cnt, p_deg, nN);
    csr_hist<<<e_grid, 256>>>(dst, p_deg, nE);
    csr_scan<<<1, 1024>>>(p_deg, p_off, p_cur, nN, nE);
    csr_place<<<e_grid, 256>>>(src, dst, p_cur, p_elist, nE);

    for (int i = 0; i < 3; i++) {
        const float* xin = (i == 0) ? x : p_x;
        const float* wsH = p_whi + (size_t)i * DD * DD;
        const float* wsL = p_wlo + (size_t)i * DD * DD;
        const float* wmH = p_whi + (size_t)(3 + i) * DD * DD;
        const float* wmL = p_wlo + (size_t)(3 + i) * DD * DD;

        gemm_dual<<<gemm_grid, 256>>>(xin, wsH, wsL, wmH, wmL,
                                      b_self + i * DD, b_msg + i * DD,
                                      p_acc, p_msg, nN);
        if (i < 2)
            gather_ln<<<row_grid, 256>>>(p_off, p_elist, p_msg, p_acc,
                                         ln_g + i * DD, ln_b + i * DD, p_x, nN);
        else
            gather_pool<<<row_grid, 256>>>(p_off, p_elist, p_msg, p_acc,
                                           batch, p_pool, p_cnt, nN);
    }

    head_kernel<<<GG, DD>>>(p_pool, p_cnt, W1, b1, W2, b2, (float*)d_out);
}

// round 7
// speedup vs baseline: 2.0920x; 1.1512x over previous
#include <cuda_runtime.h>
#include <math.h>
#include <stdint.h>

#define NN_MAX 50000
#define NE_MAX 1000000
#define DD 128
#define GG 64
#define CC 32
#define EPS 1e-5f
#define SCAN_B 256
#define NB_MAX ((NN_MAX + SCAN_B - 1) / SCAN_B)

// ---------------- scratch (no allocation allowed) ----------------
__device__ float g_acc[(size_t)NN_MAX * DD];   // self-linear result
__device__ float g_msg[(size_t)NN_MAX * DD];   // message-linear result
__device__ float g_x  [(size_t)NN_MAX * DD];   // activations between layers
__device__ float g_pool[GG * DD];
__device__ float g_cnt [GG];
__device__ float g_whi[6 * DD * DD];           // tf32 hi of all 6 weight mats
__device__ float g_wlo[6 * DD * DD];           // tf32 lo
__device__ int   g_deg[NN_MAX];                // CSR: per-dst degree
__device__ int   g_off[NN_MAX + 1];            // CSR: row offsets
__device__ int   g_cur[NN_MAX];                // CSR: placement cursors
__device__ int   g_elist[NE_MAX];              // CSR: src list grouped by dst
__device__ int   g_bsum[NB_MAX];               // per-block sums for scan

__device__ __forceinline__ uint32_t f2tf32(float x)
{
    uint32_t r;
    asm("cvt.rna.tf32.f32 %0, %1;" : "=r"(r) : "f"(x));
    return r;
}

__device__ __forceinline__ void mma8(float* c, const uint32_t* a,
                                     uint32_t b0, uint32_t b1)
{
    asm volatile(
        "mma.sync.aligned.m16n8k8.row.col.f32.tf32.tf32.f32 "
        "{%0,%1,%2,%3},{%4,%5,%6,%7},{%8,%9},{%0,%1,%2,%3};"
        : "+f"(c[0]), "+f"(c[1]), "+f"(c[2]), "+f"(c[3])
        : "r"(a[0]), "r"(a[1]), "r"(a[2]), "r"(a[3]), "r"(b0), "r"(b1));
}

// ---------------- weight split: W -> (tf32 hi, tf32 lo) ----------------
__global__ void wsplit(const float* __restrict__ Wself,
                       const float* __restrict__ Wmsg,
                       float* __restrict__ whi, float* __restrict__ wlo)
{
    const int n = 3 * DD * DD;
    int i = blockIdx.x * blockDim.x + threadIdx.x;
    if (i >= 2 * n) return;
    float x = (i < n) ? Wself[i] : Wmsg[i - n];
    uint32_t h = f2tf32(x);
    float hf = __uint_as_float(h);
    uint32_t l = f2tf32(x - hf);
    whi[i] = hf;
    wlo[i] = __uint_as_float(l);
}

// ---------------- CSR build ----------------
__global__ void zero_misc(float* pool, float* cnt, int* deg, int nN)
{
    const int t = blockIdx.x * blockDim.x + threadIdx.x;
    if (t < GG * DD) pool[t] = 0.f;
    if (t < GG) cnt[t] = 0.f;
    if (t < nN) deg[t] = 0;
}

__global__ void csr_hist(const int* __restrict__ dst, int* __restrict__ deg,
                         int nE)
{
    int e = blockIdx.x * blockDim.x + threadIdx.x;
    if (e < nE) atomicAdd(&deg[dst[e]], 1);
}

// scan stage 1: per-block sums of deg
__global__ void __launch_bounds__(SCAN_B) csr_bsum(const int* __restrict__ deg,
                                                   int* __restrict__ bsum, int nN)
{
    __shared__ int sm[SCAN_B];
    const int t = threadIdx.x;
    const int i = blockIdx.x * SCAN_B + t;
    sm[t] = (i < nN) ? deg[i] : 0;
    __syncthreads();
#pragma unroll
    for (int o = SCAN_B / 2; o; o >>= 1) {
        if (t < o) sm[t] += sm[t + o];
        __syncthreads();
    }
    if (t == 0) bsum[blockIdx.x] = sm[0];
}

// scan stage 2: exclusive scan of block sums (nB <= 256), single block
__global__ void __launch_bounds__(SCAN_B) csr_bscan(int* __restrict__ bsum, int nB)
{
    __shared__ int wsum[8];
    const int t = threadIdx.x;
    const int lane = t & 31;
    const int w = t >> 5;
    int v = (t < nB) ? bsum[t] : 0;
    int x = v;
#pragma unroll
    for (int o = 1; o < 32; o <<= 1) {
        int y = __shfl_up_sync(0xffffffffu, x, o);
        if (lane >= o) x += y;
    }
    if (lane == 31) wsum[w] = x;
    __syncthreads();
    if (t < 8) {
        int s = wsum[t];
#pragma unroll
        for (int o = 1; o < 8; o <<= 1) {
            int y = __shfl_up_sync(0xffu, s, o);
            if (t >= o) s += y;
        }
        wsum[t] = s;
    }
    __syncthreads();
    int wo = (w == 0) ? 0 : wsum[w - 1];
    if (t < nB) bsum[t] = wo + x - v;   // exclusive
}

// scan stage 3: per-block exclusive scan + block offset -> off, cur
__global__ void __launch_bounds__(SCAN_B) csr_write(const int* __restrict__ deg,
                                                    const int* __restrict__ bsum,
                                                    int* __restrict__ off,
                                                    int* __restrict__ cur,
                                                    int nN, int nE)
{
    __shared__ int wsum[8];
    const int t = threadIdx.x;
    const int lane = t & 31;
    const int w = t >> 5;
    const int i = blockIdx.x * SCAN_B + t;
    int v = (i < nN) ? deg[i] : 0;
    int x = v;
#pragma unroll
    for (int o = 1; o < 32; o <<= 1) {
        int y = __shfl_up_sync(0xffffffffu, x, o);
        if (lane >= o) x += y;
    }
    if (lane == 31) wsum[w] = x;
    __syncthreads();
    if (t < 8) {
        int s = wsum[t];
#pragma unroll
        for (int o = 1; o < 8; o <<= 1) {
            int y = __shfl_up_sync(0xffu, s, o);
            if (t >= o) s += y;
        }
        wsum[t] = s;
    }
    __syncthreads();
    int wo = (w == 0) ? 0 : wsum[w - 1];
    int excl = bsum[blockIdx.x] + wo + x - v;
    if (i < nN) {
        off[i] = excl;
        cur[i] = excl;
    }
    if (i == nN - 1) off[nN] = nE;
}

__global__ void csr_place(const int* __restrict__ src,
                          const int* __restrict__ dst,
                          int* __restrict__ cur, int* __restrict__ elist, int nE)
{
    int e = blockIdx.x * blockDim.x + threadIdx.x;
    if (e < nE) {
        int p = atomicAdd(&cur[dst[e]], 1);
        elist[p] = src[e];
    }
}

// ---------------- fused dual GEMM (tf32 hi/lo): Ys = X@Ws+bs, Ym = X@Wm+bm ----
// CTA: 64 rows; warps 0-3 -> self, warps 4-7 -> msg (shared X tile)
__global__ void __launch_bounds__(256) gemm_dual(const float* __restrict__ X,
                                                 const float* __restrict__ WsH,
                                                 const float* __restrict__ WsL,
                                                 const float* __restrict__ WmH,
                                                 const float* __restrict__ WmL,
                                                 const float* __restrict__ bS,
                                                 const float* __restrict__ bM,
                                                 float* __restrict__ Ys,
                                                 float* __restrict__ Ym, int nrows)
{
    __shared__ float Xs[64][20];        // pad: conflict-free A-frag loads
    __shared__ float Bs[4][16][136];    // 0=WsH 1=WsL 2=WmH 3=WmL

    const int tid  = threadIdx.x;
    const int lane = tid & 31;
    const int warp = tid >> 5;
    const int half = warp >> 2;         // 0: self, 1: msg
    const int wr   = (warp & 3) * 16;   // 16-row slab within 64
    const int row0 = blockIdx.x * 64;
    const int gid  = lane >> 2;
    const int tig  = lane & 3;

    float c[16][4];
#pragma unroll
    for (int t = 0; t < 16; t++)
#pragma unroll
        for (int j = 0; j < 4; j++) c[t][j] = 0.f;

    for (int k0 = 0; k0 < DD; k0 += 16) {
        // stage X tile [64 x 16]: 256 float4s, one per thread
        {
            int r  = tid >> 2;
            int cc = (tid & 3) * 4;
            float4 v = make_float4(0.f, 0.f, 0.f, 0.f);
            int gr = row0 + r;
            if (gr < nrows)
                v = *reinterpret_cast<const float4*>(&X[(size_t)gr * DD + k0 + cc]);
            *reinterpret_cast<float4*>(&Xs[r][cc]) = v;
        }
        // stage all 4 W tiles [16 x 128]: 4 x 512 float4, 8 per thread
#pragma unroll
        for (int m = 0; m < 4; m++) {
            const float* Wp = (m == 0) ? WsH : (m == 1) ? WsL : (m == 2) ? WmH : WmL;
#pragma unroll
            for (int j = 0; j < 2; j++) {
                int fidx = tid * 2 + j;            // 0..511
                int k = fidx >> 5;
                int n = (fidx & 31) * 4;
                *reinterpret_cast<float4*>(&Bs[m][k][n]) =
                    *reinterpret_cast<const float4*>(&Wp[(size_t)(k0 + k) * DD + n]);
            }
        }
        __syncthreads();

#pragma unroll
        for (int kc = 0; kc < 2; kc++) {
            uint32_t ah[4], al[4];
#pragma unroll
            for (int i = 0; i < 4; i++) {
                int rr = wr + gid + (i & 1) * 8;
                int cc = kc * 8 + tig + (i >> 1) * 4;
                float a = Xs[rr][cc];
                ah[i] = f2tf32(a);
                al[i] = f2tf32(a - __uint_as_float(ah[i]));
            }
            const int hi = half * 2, lo = half * 2 + 1;
#pragma unroll
            for (int t = 0; t < 16; t++) {
                int n = t * 8 + gid;
                uint32_t bh0 = __float_as_uint(Bs[hi][kc * 8 + tig]    [n]);
                uint32_t bh1 = __float_as_uint(Bs[hi][kc * 8 + tig + 4][n]);
                uint32_t bl0 = __float_as_uint(Bs[lo][kc * 8 + tig]    [n]);
                uint32_t bl1 = __float_as_uint(Bs[lo][kc * 8 + tig + 4][n]);
                mma8(c[t], ah, bh0, bh1);   // hi*hi
                mma8(c[t], ah, bl0, bl1);   // hi*lo
                mma8(c[t], al, bh0, bh1);   // lo*hi
            }
        }
        __syncthreads();
    }

    float* Y = half ? Ym : Ys;
    const float* bias = half ? bM : bS;
#pragma unroll
    for (int t = 0; t < 16; t++) {
        int col = t * 8 + tig * 2;
        float2 b = *reinterpret_cast<const float2*>(&bias[col]);
        int r = row0 + wr + gid;
        if (r < nrows) {
            float2 o; o.x = c[t][0] + b.x; o.y = c[t][1] + b.y;
            *reinterpret_cast<float2*>(&Y[(size_t)r * DD + col]) = o;
        }
        int r2 = r + 8;
        if (r2 < nrows) {
            float2 o; o.x = c[t][2] + b.x; o.y = c[t][3] + b.y;
            *reinterpret_cast<float2*>(&Y[(size_t)r2 * DD + col]) = o;
        }
    }
}

// ---------------- gather (CSR) + ReLU + LayerNorm, warp per node ----------------
__global__ void __launch_bounds__(256) gather_ln(const int* __restrict__ off,
                                                 const int* __restrict__ elist,
                                                 const float* __restrict__ msg,
                                                 const float* __restrict__ selfv,
                                                 const float* __restrict__ lg,
                                                 const float* __restrict__ lb,
                                                 float* __restrict__ out, int nN)
{
    const int lane = threadIdx.x & 31;
    const int row  = (blockIdx.x * blockDim.x + threadIdx.x) >> 5;
    if (row >= nN) return;

    float4 a0 = *reinterpret_cast<const float4*>(&selfv[(size_t)row * DD + lane * 4]);
    float4 a1 = make_float4(0.f, 0.f, 0.f, 0.f);

    const int b = __ldg(&off[row]);
    const int e = __ldg(&off[row + 1]);
    int i = b;
    for (; i + 2 <= e; i += 2) {
        int s0 = __ldg(&elist[i]);
        int s1 = __ldg(&elist[i + 1]);
        float4 v0 = *reinterpret_cast<const float4*>(&msg[(size_t)s0 * DD + lane * 4]);
        float4 v1 = *reinterpret_cast<const float4*>(&msg[(size_t)s1 * DD + lane * 4]);
        a0.x += v0.x; a0.y += v0.y; a0.z += v0.z; a0.w += v0.w;
        a1.x += v1.x; a1.y += v1.y; a1.z += v1.z; a1.w += v1.w;
    }
    if (i < e) {
        int s0 = __ldg(&elist[i]);
        float4 v0 = *reinterpret_cast<const float4*>(&msg[(size_t)s0 * DD + lane * 4]);
        a0.x += v0.x; a0.y += v0.y; a0.z += v0.z; a0.w += v0.w;
    }
    float4 v;
    v.x = fmaxf(a0.x + a1.x, 0.f);
    v.y = fmaxf(a0.y + a1.y, 0.f);
    v.z = fmaxf(a0.z + a1.z, 0.f);
    v.w = fmaxf(a0.w + a1.w, 0.f);

    float s  = v.x + v.y + v.z + v.w;
    float ss = v.x * v.x + v.y * v.y + v.z * v.z + v.w * v.w;
#pragma unroll
    for (int o = 16; o; o >>= 1) {
        s  += __shfl_xor_sync(0xffffffffu, s,  o);
        ss += __shfl_xor_sync(0xffffffffu, ss, o);
    }
    const float mu  = s * (1.f / 128.f);
    const float var = ss * (1.f / 128.f) - mu * mu;
    const float inv = rsqrtf(var + EPS);

    const float4 gv = *reinterpret_cast<const float4*>(&lg[lane * 4]);
    const float4 bv = *reinterpret_cast<const float4*>(&lb[lane * 4]);
    float4 o4;
    o4.x = gv.x * (v.x - mu) * inv + bv.x;
    o4.y = gv.y * (v.y - mu) * inv + bv.y;
    o4.z = gv.z * (v.z - mu) * inv + bv.z;
    o4.w = gv.w * (v.w - mu) * inv + bv.w;
    *reinterpret_cast<float4*>(&out[(size_t)row * DD + lane * 4]) = o4;
}

// ---------------- gather (CSR) + ReLU + pool, warp per node ----------------
__global__ void __launch_bounds__(256) gather_pool(const int* __restrict__ off,
                                                   const int* __restrict__ elist,
                                                   const float* __restrict__ msg,
                                                   const float* __restrict__ selfv,
                                                   const int* __restrict__ batch,
                                                   float* __restrict__ pool,
                                                   float* __restrict__ cnt, int nN)
{
    const int lane = threadIdx.x & 31;
    const int row  = (blockIdx.x * blockDim.x + threadIdx.x) >> 5;
    if (row >= nN) return;

    float4 a0 = *reinterpret_cast<const float4*>(&selfv[(size_t)row * DD + lane * 4]);
    float4 a1 = make_float4(0.f, 0.f, 0.f, 0.f);

    const int b = __ldg(&off[row]);
    const int e = __ldg(&off[row + 1]);
    int i = b;
    for (; i + 2 <= e; i += 2) {
        int s0 = __ldg(&elist[i]);
        int s1 = __ldg(&elist[i + 1]);
        float4 v0 = *reinterpret_cast<const float4*>(&msg[(size_t)s0 * DD + lane * 4]);
        float4 v1 = *reinterpret_cast<const float4*>(&msg[(size_t)s1 * DD + lane * 4]);
        a0.x += v0.x; a0.y += v0.y; a0.z += v0.z; a0.w += v0.w;
        a1.x += v1.x; a1.y += v1.y; a1.z += v1.z; a1.w += v1.w;
    }
    if (i < e) {
        int s0 = __ldg(&elist[i]);
        float4 v0 = *reinterpret_cast<const float4*>(&msg[(size_t)s0 * DD + lane * 4]);
        a0.x += v0.x; a0.y += v0.y; a0.z += v0.z; a0.w += v0.w;
    }
    float4 v;
    v.x = fmaxf(a0.x + a1.x, 0.f);
    v.y = fmaxf(a0.y + a1.y, 0.f);
    v.z = fmaxf(a0.z + a1.z, 0.f);
    v.w = fmaxf(a0.w + a1.w, 0.f);

    const int g = __ldg(&batch[row]);
    float* p = &pool[(size_t)g * DD + lane * 4];
    asm volatile("red.global.add.v4.f32 [%0], {%1,%2,%3,%4};"
                 :: "l"(p), "f"(v.x), "f"(v.y), "f"(v.z), "f"(v.w) : "memory");
    if (lane == 0) atomicAdd(&cnt[g], 1.0f);
}

// ---------------- head: mean, 2 linears, log_softmax ----------------
__global__ void __launch_bounds__(DD) head_kernel(const float* __restrict__ pool,
                                                  const float* __restrict__ cnt,
                                                  const float* __restrict__ W1,
                                                  const float* __restrict__ b1,
                                                  const float* __restrict__ W2,
                                                  const float* __restrict__ b2,
                                                  float* __restrict__ out)
{
    __shared__ float p[DD];
    __shared__ float h[DD];
    const int g = blockIdx.x;
    const int t = threadIdx.x;

    const float c = fmaxf(cnt[g], 1.f);
    p[t] = pool[g * DD + t] / c;
    __syncthreads();

    float a = b1[t];
#pragma unroll 8
    for (int k = 0; k < DD; k++) a += p[k] * W1[k * DD + t];
    h[t] = a;
    __syncthreads();

    if (t < CC) {
        float l = b2[t];
#pragma unroll 8
        for (int d = 0; d < DD; d++) l += h[d] * W2[d * CC + t];

        float m = l;
#pragma unroll
        for (int o = 16; o; o >>= 1) m = fmaxf(m, __shfl_xor_sync(0xffffffffu, m, o));
        float e = expf(l - m);
        float s = e;
#pragma unroll
        for (int o = 16; o; o >>= 1) s += __shfl_xor_sync(0xffffffffu, s, o);
        out[g * CC + t] = l - m - logf(s);
    }
}

// ---------------- launch ----------------
extern "C" void kernel_launch(void* const* d_in, const int* in_sizes, int n_in,
                              void* d_out, int out_size)
{
    const float* x      = (const float*)d_in[0];
    const float* W_self = (const float*)d_in[1];
    const float* b_self = (const float*)d_in[2];
    const float* W_msg  = (const float*)d_in[3];
    const float* b_msg  = (const float*)d_in[4];
    const float* ln_g   = (const float*)d_in[5];
    const float* ln_b   = (const float*)d_in[6];
    const float* W1     = (const float*)d_in[7];
    const float* b1     = (const float*)d_in[8];
    const float* W2     = (const float*)d_in[9];
    const float* b2     = (const float*)d_in[10];
    const int*   eidx   = (const int*)d_in[11];
    const int*   batch  = (const int*)d_in[12];

    const int nN = in_sizes[0] / DD;
    const int nE = in_sizes[11] / 2;
    const int* src = eidx;
    const int* dst = eidx + nE;

    float *p_acc, *p_msg, *p_x, *p_pool, *p_cnt, *p_whi, *p_wlo;
    int *p_deg, *p_off, *p_cur, *p_elist, *p_bsum;
    cudaGetSymbolAddress((void**)&p_acc,   g_acc);
    cudaGetSymbolAddress((void**)&p_msg,   g_msg);
    cudaGetSymbolAddress((void**)&p_x,     g_x);
    cudaGetSymbolAddress((void**)&p_pool,  g_pool);
    cudaGetSymbolAddress((void**)&p_cnt,   g_cnt);
    cudaGetSymbolAddress((void**)&p_whi,   g_whi);
    cudaGetSymbolAddress((void**)&p_wlo,   g_wlo);
    cudaGetSymbolAddress((void**)&p_deg,   g_deg);
    cudaGetSymbolAddress((void**)&p_off,   g_off);
    cudaGetSymbolAddress((void**)&p_cur,   g_cur);
    cudaGetSymbolAddress((void**)&p_elist, g_elist);
    cudaGetSymbolAddress((void**)&p_bsum,  g_bsum);

    const int gemm_grid = (nN + 63) / 64;
    const int row_grid  = (nN + 7) / 8;
    const int e_grid    = (nE + 255) / 256;
    const int nB        = (nN + SCAN_B - 1) / SCAN_B;

    wsplit<<<(6 * DD * DD + 255) / 256, 256>>>(W_self, W_msg, p_whi, p_wlo);
    zero_misc<<<(nN + 255) / 256, 256>>>(p_pool, p_cnt, p_deg, nN);
    csr_hist<<<e_grid, 256>>>(dst, p_deg, nE);
    csr_bsum<<<nB, SCAN_B>>>(p_deg, p_bsum, nN);
    csr_bscan<<<1, SCAN_B>>>(p_bsum, nB);
    csr_write<<<nB, SCAN_B>>>(p_deg, p_bsum, p_off, p_cur, nN, nE);
    csr_place<<<e_grid, 256>>>(src, dst, p_cur, p_elist, nE);

    for (int i = 0; i < 3; i++) {
        const float* xin = (i == 0) ? x : p_x;
        const float* wsH = p_whi + (size_t)i * DD * DD;
        const float* wsL = p_wlo + (size_t)i * DD * DD;
        const float* wmH = p_whi + (size_t)(3 + i) * DD * DD;
        const float* wmL = p_wlo + (size_t)(3 + i) * DD * DD;

        gemm_dual<<<gemm_grid, 256>>>(xin, wsH, wsL, wmH, wmL,
                                      b_self + i * DD, b_msg + i * DD,
                                      p_acc, p_msg, nN);
        if (i < 2)
            gather_ln<<<row_grid, 256>>>(p_off, p_elist, p_msg, p_acc,
                                         ln_g + i * DD, ln_b + i * DD, p_x, nN);
        else
            gather_pool<<<row_grid, 256>>>(p_off, p_elist, p_msg, p_acc,
                                           batch, p_pool, p_cnt, nN);
    }

    head_kernel<<<GG, DD>>>(p_pool, p_cnt, W1, b1, W2, b2, (float*)d_out);
}

// round 8
// speedup vs baseline: 2.3037x; 1.1012x over previous
#include <cuda_runtime.h>
#include <math.h>
#include <stdint.h>

#define NN_MAX 50000
#define NE_MAX 1000000
#define DD 128
#define GG 64
#define CC 32
#define EPS 1e-5f
#define SCAN_B 256
#define NB_MAX ((NN_MAX + SCAN_B - 1) / SCAN_B)

// ---------------- scratch (no allocation allowed) ----------------
__device__ float g_acc[(size_t)NN_MAX * DD];   // self-linear result
__device__ float g_msg[(size_t)NN_MAX * DD];   // message-linear result
__device__ float g_x  [(size_t)NN_MAX * DD];   // activations between layers
__device__ float g_pool[GG * DD];
__device__ float g_cnt [GG];
__device__ float g_whi[6 * DD * DD];           // tf32 hi of all 6 weight mats
__device__ float g_wlo[6 * DD * DD];           // tf32 lo
__device__ int   g_deg[NN_MAX];                // CSR: per-dst degree
__device__ int   g_off[NN_MAX + 1];            // CSR: row offsets
__device__ int   g_cur[NN_MAX];                // CSR: placement cursors
__device__ int   g_elist[NE_MAX];              // CSR: src list grouped by dst
__device__ int   g_bsum[NB_MAX];               // per-block sums for scan

__device__ __forceinline__ uint32_t f2tf32(float x)
{
    uint32_t r;
    asm("cvt.rna.tf32.f32 %0, %1;" : "=r"(r) : "f"(x));
    return r;
}

__device__ __forceinline__ void mma8(float* c, const uint32_t* a,
                                     uint32_t b0, uint32_t b1)
{
    asm volatile(
        "mma.sync.aligned.m16n8k8.row.col.f32.tf32.tf32.f32 "
        "{%0,%1,%2,%3},{%4,%5,%6,%7},{%8,%9},{%0,%1,%2,%3};"
        : "+f"(c[0]), "+f"(c[1]), "+f"(c[2]), "+f"(c[3])
        : "r"(a[0]), "r"(a[1]), "r"(a[2]), "r"(a[3]), "r"(b0), "r"(b1));
}

__device__ __forceinline__ uint32_t smem_u32(const void* p)
{
    uint32_t a;
    asm("{ .reg .u64 t; cvta.to.shared.u64 t, %1; cvt.u32.u64 %0, t; }"
        : "=r"(a) : "l"(p));
    return a;
}

__device__ __forceinline__ void cp16(uint32_t dst, const void* src, bool pred)
{
    int sz = pred ? 16 : 0;
    asm volatile("cp.async.cg.shared.global [%0], [%1], 16, %2;"
                 :: "r"(dst), "l"(src), "r"(sz));
}
#define CP_COMMIT() asm volatile("cp.async.commit_group;" ::: "memory")

// ---------------- weight split: W -> (tf32 hi, tf32 lo) ----------------
__global__ void wsplit(const float* __restrict__ Wself,
                       const float* __restrict__ Wmsg,
                       float* __restrict__ whi, float* __restrict__ wlo)
{
    const int n = 3 * DD * DD;
    int i = blockIdx.x * blockDim.x + threadIdx.x;
    if (i >= 2 * n) return;
    float x = (i < n) ? Wself[i] : Wmsg[i - n];
    uint32_t h = f2tf32(x);
    float hf = __uint_as_float(h);
    uint32_t l = f2tf32(x - hf);
    whi[i] = hf;
    wlo[i] = __uint_as_float(l);
}

// ---------------- CSR build ----------------
__global__ void zero_misc(float* pool, float* cnt, int* deg, int nN)
{
    const int t = blockIdx.x * blockDim.x + threadIdx.x;
    if (t < GG * DD) pool[t] = 0.f;
    if (t < GG) cnt[t] = 0.f;
    if (t < nN) deg[t] = 0;
}

__global__ void csr_hist(const int* __restrict__ dst, int* __restrict__ deg,
                         int nE)
{
    int e = blockIdx.x * blockDim.x + threadIdx.x;
    if (e < nE) atomicAdd(&deg[dst[e]], 1);
}

__global__ void __launch_bounds__(SCAN_B) csr_bsum(const int* __restrict__ deg,
                                                   int* __restrict__ bsum, int nN)
{
    __shared__ int sm[SCAN_B];
    const int t = threadIdx.x;
    const int i = blockIdx.x * SCAN_B + t;
    sm[t] = (i < nN) ? deg[i] : 0;
    __syncthreads();
#pragma unroll
    for (int o = SCAN_B / 2; o; o >>= 1) {
        if (t < o) sm[t] += sm[t + o];
        __syncthreads();
    }
    if (t == 0) bsum[blockIdx.x] = sm[0];
}

__global__ void __launch_bounds__(SCAN_B) csr_bscan(int* __restrict__ bsum, int nB)
{
    __shared__ int wsum[8];
    const int t = threadIdx.x;
    const int lane = t & 31;
    const int w = t >> 5;
    int v = (t < nB) ? bsum[t] : 0;
    int x = v;
#pragma unroll
    for (int o = 1; o < 32; o <<= 1) {
        int y = __shfl_up_sync(0xffffffffu, x, o);
        if (lane >= o) x += y;
    }
    if (lane == 31) wsum[w] = x;
    __syncthreads();
    if (t < 8) {
        int s = wsum[t];
#pragma unroll
        for (int o = 1; o < 8; o <<= 1) {
            int y = __shfl_up_sync(0xffu, s, o);
            if (t >= o) s += y;
        }
        wsum[t] = s;
    }
    __syncthreads();
    int wo = (w == 0) ? 0 : wsum[w - 1];
    if (t < nB) bsum[t] = wo + x - v;   // exclusive
}

__global__ void __launch_bounds__(SCAN_B) csr_write(const int* __restrict__ deg,
                                                    const int* __restrict__ bsum,
                                                    int* __restrict__ off,
                                                    int* __restrict__ cur,
                                                    int nN, int nE)
{
    __shared__ int wsum[8];
    const int t = threadIdx.x;
    const int lane = t & 31;
    const int w = t >> 5;
    const int i = blockIdx.x * SCAN_B + t;
    int v = (i < nN) ? deg[i] : 0;
    int x = v;
#pragma unroll
    for (int o = 1; o < 32; o <<= 1) {
        int y = __shfl_up_sync(0xffffffffu, x, o);
        if (lane >= o) x += y;
    }
    if (lane == 31) wsum[w] = x;
    __syncthreads();
    if (t < 8) {
        int s = wsum[t];
#pragma unroll
        for (int o = 1; o < 8; o <<= 1) {
            int y = __shfl_up_sync(0xffu, s, o);
            if (t >= o) s += y;
        }
        wsum[t] = s;
    }
    __syncthreads();
    int wo = (w == 0) ? 0 : wsum[w - 1];
    int excl = bsum[blockIdx.x] + wo + x - v;
    if (i < nN) {
        off[i] = excl;
        cur[i] = excl;
    }
    if (i == nN - 1) off[nN] = nE;
}

__global__ void csr_place(const int* __restrict__ src,
                          const int* __restrict__ dst,
                          int* __restrict__ cur, int* __restrict__ elist, int nE)
{
    int e = blockIdx.x * blockDim.x + threadIdx.x;
    if (e < nE) {
        int p = atomicAdd(&cur[dst[e]], 1);
        elist[p] = src[e];
    }
}

// ---------------- fused dual GEMM v2: 32x64 warp tiles + cp.async 2-stage ----
// CTA: 64 rows; warp = {half, rowslab, colhalf}; dynamic smem double buffer.
// stage layout (bytes): X 64x20 floats (5120), then 4 W mats 16x136 floats
#define STG_B   39936
#define XB      5120
#define WMATB   8704

__global__ void __launch_bounds__(256) gemm_dual(const float* __restrict__ X,
                                                 const float* __restrict__ WsH,
                                                 const float* __restrict__ WsL,
                                                 const float* __restrict__ WmH,
                                                 const float* __restrict__ WmL,
                                                 const float* __restrict__ bS,
                                                 const float* __restrict__ bM,
                                                 float* __restrict__ Ys,
                                                 float* __restrict__ Ym, int nrows)
{
    extern __shared__ char smem[];
    const uint32_t sb = smem_u32(smem);

    const int tid  = threadIdx.x;
    const int lane = tid & 31;
    const int warp = tid >> 5;
    const int half = warp >> 2;          // 0: self, 1: msg
    const int rs   = (warp >> 1) & 1;    // row slab (32 rows)
    const int ch   = warp & 1;           // col half (64 cols)
    const int row0 = blockIdx.x * 64;
    const int gid  = lane >> 2;
    const int tig  = lane & 3;

    const float* Wmats[4];
    Wmats[0] = WsH; Wmats[1] = WsL; Wmats[2] = WmH; Wmats[3] = WmL;

    // load helpers (cp.async)
    const int xr  = tid >> 2;            // X: row
    const int xc  = (tid & 3) * 4;       // X: col group
    float c[2][8][4];
#pragma unroll
    for (int s = 0; s < 2; s++)
#pragma unroll
        for (int t = 0; t < 8; t++)
#pragma unroll
            for (int j = 0; j < 4; j++) c[s][t][j] = 0.f;

    // prologue: stage 0, k0 = 0
    {
        const int gr = row0 + xr;
        cp16(sb + xr * 80 + xc * 4, &X[(size_t)gr * DD + xc], gr < nrows);
#pragma unroll
        for (int m = 0; m < 4; m++)
#pragma unroll
            for (int j = 0; j < 2; j++) {
                int fidx = tid * 2 + j;
                int k = fidx >> 5;
                int n = (fidx & 31) * 4;
                cp16(sb + XB + m * WMATB + k * 544 + n * 4,
                     &Wmats[m][(size_t)k * DD + n], true);
            }
    }
    CP_COMMIT();

    for (int it = 0; it < 8; it++) {
        const int buf = it & 1;
        if (it < 7) {
            const int k0n = (it + 1) * 16;
            const uint32_t st = sb + (buf ^ 1) * STG_B;
            const int gr = row0 + xr;
            cp16(st + xr * 80 + xc * 4, &X[(size_t)gr * DD + k0n + xc], gr < nrows);
#pragma unroll
            for (int m = 0; m < 4; m++)
#pragma unroll
                for (int j = 0; j < 2; j++) {
                    int fidx = tid * 2 + j;
                    int k = fidx >> 5;
                    int n = (fidx & 31) * 4;
                    cp16(st + XB + m * WMATB + k * 544 + n * 4,
                         &Wmats[m][(size_t)(k0n + k) * DD + n], true);
                }
            CP_COMMIT();
            asm volatile("cp.async.wait_group 1;" ::: "memory");
        } else {
            asm volatile("cp.async.wait_group 0;" ::: "memory");
        }
        __syncthreads();

        const float* Xs = (const float*)(smem + buf * STG_B);
        const float* Bh = (const float*)(smem + buf * STG_B + XB + (half * 2) * WMATB);
        const float* Bl = (const float*)(smem + buf * STG_B + XB + (half * 2 + 1) * WMATB);

#pragma unroll
        for (int kc = 0; kc < 2; kc++) {
            uint32_t ah[2][4], al[2][4];
#pragma unroll
            for (int s = 0; s < 2; s++)
#pragma unroll
                for (int i = 0; i < 4; i++) {
                    int rr = rs * 32 + s * 16 + gid + (i & 1) * 8;
                    int cc = kc * 8 + tig + (i >> 1) * 4;
                    float a = Xs[rr * 20 + cc];
                    ah[s][i] = f2tf32(a);
                    al[s][i] = f2tf32(a - __uint_as_float(ah[s][i]));
                }
#pragma unroll
            for (int t = 0; t < 8; t++) {
                int n  = ch * 64 + t * 8 + gid;
                int r0 = (kc * 8 + tig) * 136 + n;
                int r1 = (kc * 8 + tig + 4) * 136 + n;
                uint32_t bh0 = __float_as_uint(Bh[r0]);
                uint32_t bh1 = __float_as_uint(Bh[r1]);
                uint32_t bl0 = __float_as_uint(Bl[r0]);
                uint32_t bl1 = __float_as_uint(Bl[r1]);
#pragma unroll
                for (int s = 0; s < 2; s++) {
                    mma8(c[s][t], ah[s], bh0, bh1);   // hi*hi
                    mma8(c[s][t], ah[s], bl0, bl1);   // hi*lo
                    mma8(c[s][t], al[s], bh0, bh1);   // lo*hi
                }
            }
        }
        __syncthreads();
    }

    float* Y = half ? Ym : Ys;
    const float* bias = half ? bM : bS;
#pragma unroll
    for (int s = 0; s < 2; s++)
#pragma unroll
        for (int t = 0; t < 8; t++) {
            int col = ch * 64 + t * 8 + tig * 2;
            float2 b = *reinterpret_cast<const float2*>(&bias[col]);
            int r = row0 + rs * 32 + s * 16 + gid;
            if (r < nrows) {
                float2 o; o.x = c[s][t][0] + b.x; o.y = c[s][t][1] + b.y;
                *reinterpret_cast<float2*>(&Y[(size_t)r * DD + col]) = o;
            }
            int r2 = r + 8;
            if (r2 < nrows) {
                float2 o; o.x = c[s][t][2] + b.x; o.y = c[s][t][3] + b.y;
                *reinterpret_cast<float2*>(&Y[(size_t)r2 * DD + col]) = o;
            }
        }
}

// ---------------- gather (CSR) + ReLU + LayerNorm, warp per node ----------------
__global__ void __launch_bounds__(256) gather_ln(const int* __restrict__ off,
                                                 const int* __restrict__ elist,
                                                 const float* __restrict__ msg,
                                                 const float* __restrict__ selfv,
                                                 const float* __restrict__ lg,
                                                 const float* __restrict__ lb,
                                                 float* __restrict__ out, int nN)
{
    const int lane = threadIdx.x & 31;
    const int row  = (blockIdx.x * blockDim.x + threadIdx.x) >> 5;
    if (row >= nN) return;

    float4 a0 = *reinterpret_cast<const float4*>(&selfv[(size_t)row * DD + lane * 4]);
    float4 a1 = make_float4(0.f, 0.f, 0.f, 0.f);

    const int b = __ldg(&off[row]);
    const int e = __ldg(&off[row + 1]);
    int i = b;
    for (; i + 2 <= e; i += 2) {
        int s0 = __ldg(&elist[i]);
        int s1 = __ldg(&elist[i + 1]);
        float4 v0 = *reinterpret_cast<const float4*>(&msg[(size_t)s0 * DD + lane * 4]);
        float4 v1 = *reinterpret_cast<const float4*>(&msg[(size_t)s1 * DD + lane * 4]);
        a0.x += v0.x; a0.y += v0.y; a0.z += v0.z; a0.w += v0.w;
        a1.x += v1.x; a1.y += v1.y; a1.z += v1.z; a1.w += v1.w;
    }
    if (i < e) {
        int s0 = __ldg(&elist[i]);
        float4 v0 = *reinterpret_cast<const float4*>(&msg[(size_t)s0 * DD + lane * 4]);
        a0.x += v0.x; a0.y += v0.y; a0.z += v0.z; a0.w += v0.w;
    }
    float4 v;
    v.x = fmaxf(a0.x + a1.x, 0.f);
    v.y = fmaxf(a0.y + a1.y, 0.f);
    v.z = fmaxf(a0.z + a1.z, 0.f);
    v.w = fmaxf(a0.w + a1.w, 0.f);

    float s  = v.x + v.y + v.z + v.w;
    float ss = v.x * v.x + v.y * v.y + v.z * v.z + v.w * v.w;
#pragma unroll
    for (int o = 16; o; o >>= 1) {
        s  += __shfl_xor_sync(0xffffffffu, s,  o);
        ss += __shfl_xor_sync(0xffffffffu, ss, o);
    }
    const float mu  = s * (1.f / 128.f);
    const float var = ss * (1.f / 128.f) - mu * mu;
    const float inv = rsqrtf(var + EPS);

    const float4 gv = *reinterpret_cast<const float4*>(&lg[lane * 4]);
    const float4 bv = *reinterpret_cast<const float4*>(&lb[lane * 4]);
    float4 o4;
    o4.x = gv.x * (v.x - mu) * inv + bv.x;
    o4.y = gv.y * (v.y - mu) * inv + bv.y;
    o4.z = gv.z * (v.z - mu) * inv + bv.z;
    o4.w = gv.w * (v.w - mu) * inv + bv.w;
    *reinterpret_cast<float4*>(&out[(size_t)row * DD + lane * 4]) = o4;
}

// ---------------- gather (CSR) + ReLU + pool, warp per node ----------------
__global__ void __launch_bounds__(256) gather_pool(const int* __restrict__ off,
                                                   const int* __restrict__ elist,
                                                   const float* __restrict__ msg,
                                                   const float* __restrict__ selfv,
                                                   const int* __restrict__ batch,
                                                   float* __restrict__ pool,
                                                   float* __restrict__ cnt, int nN)
{
    const int lane = threadIdx.x & 31;
    const int row  = (blockIdx.x * blockDim.x + threadIdx.x) >> 5;
    if (row >= nN) return;

    float4 a0 = *reinterpret_cast<const float4*>(&selfv[(size_t)row * DD + lane * 4]);
    float4 a1 = make_float4(0.f, 0.f, 0.f, 0.f);

    const int b = __ldg(&off[row]);
    const int e = __ldg(&off[row + 1]);
    int i = b;
    for (; i + 2 <= e; i += 2) {
        int s0 = __ldg(&elist[i]);
        int s1 = __ldg(&elist[i + 1]);
        float4 v0 = *reinterpret_cast<const float4*>(&msg[(size_t)s0 * DD + lane * 4]);
        float4 v1 = *reinterpret_cast<const float4*>(&msg[(size_t)s1 * DD + lane * 4]);
        a0.x += v0.x; a0.y += v0.y; a0.z += v0.z; a0.w += v0.w;
        a1.x += v1.x; a1.y += v1.y; a1.z += v1.z; a1.w += v1.w;
    }
    if (i < e) {
        int s0 = __ldg(&elist[i]);
        float4 v0 = *reinterpret_cast<const float4*>(&msg[(size_t)s0 * DD + lane * 4]);
        a0.x += v0.x; a0.y += v0.y; a0.z += v0.z; a0.w += v0.w;
    }
    float4 v;
    v.x = fmaxf(a0.x + a1.x, 0.f);
    v.y = fmaxf(a0.y + a1.y, 0.f);
    v.z = fmaxf(a0.z + a1.z, 0.f);
    v.w = fmaxf(a0.w + a1.w, 0.f);

    const int g = __ldg(&batch[row]);
    float* p = &pool[(size_t)g * DD + lane * 4];
    asm volatile("red.global.add.v4.f32 [%0], {%1,%2,%3,%4};"
                 :: "l"(p), "f"(v.x), "f"(v.y), "f"(v.z), "f"(v.w) : "memory");
    if (lane == 0) atomicAdd(&cnt[g], 1.0f);
}

// ---------------- head: mean, 2 linears, log_softmax ----------------
__global__ void __launch_bounds__(DD) head_kernel(const float* __restrict__ pool,
                                                  const float* __restrict__ cnt,
                                                  const float* __restrict__ W1,
                                                  const float* __restrict__ b1,
                                                  const float* __restrict__ W2,
                                                  const float* __restrict__ b2,
                                                  float* __restrict__ out)
{
    __shared__ float p[DD];
    __shared__ float h[DD];
    const int g = blockIdx.x;
    const int t = threadIdx.x;

    const float c = fmaxf(cnt[g], 1.f);
    p[t] = pool[g * DD + t] / c;
    __syncthreads();

    float a = b1[t];
#pragma unroll 8
    for (int k = 0; k < DD; k++) a += p[k] * W1[k * DD + t];
    h[t] = a;
    __syncthreads();

    if (t < CC) {
        float l = b2[t];
#pragma unroll 8
        for (int d = 0; d < DD; d++) l += h[d] * W2[d * CC + t];

        float m = l;
#pragma unroll
        for (int o = 16; o; o >>= 1) m = fmaxf(m, __shfl_xor_sync(0xffffffffu, m, o));
        float e = expf(l - m);
        float s = e;
#pragma unroll
        for (int o = 16; o; o >>= 1) s += __shfl_xor_sync(0xffffffffu, s, o);
        out[g * CC + t] = l - m - logf(s);
    }
}

// ---------------- launch ----------------
extern "C" void kernel_launch(void* const* d_in, const int* in_sizes, int n_in,
                              void* d_out, int out_size)
{
    const float* x      = (const float*)d_in[0];
    const float* W_self = (const float*)d_in[1];
    const float* b_self = (const float*)d_in[2];
    const float* W_msg  = (const float*)d_in[3];
    const float* b_msg  = (const float*)d_in[4];
    const float* ln_g   = (const float*)d_in[5];
    const float* ln_b   = (const float*)d_in[6];
    const float* W1     = (const float*)d_in[7];
    const float* b1     = (const float*)d_in[8];
    const float* W2     = (const float*)d_in[9];
    const float* b2     = (const float*)d_in[10];
    const int*   eidx   = (const int*)d_in[11];
    const int*   batch  = (const int*)d_in[12];

    const int nN = in_sizes[0] / DD;
    const int nE = in_sizes[11] / 2;
    const int* src = eidx;
    const int* dst = eidx + nE;

    float *p_acc, *p_msg, *p_x, *p_pool, *p_cnt, *p_whi, *p_wlo;
    int *p_deg, *p_off, *p_cur, *p_elist, *p_bsum;
    cudaGetSymbolAddress((void**)&p_acc,   g_acc);
    cudaGetSymbolAddress((void**)&p_msg,   g_msg);
    cudaGetSymbolAddress((void**)&p_x,     g_x);
    cudaGetSymbolAddress((void**)&p_pool,  g_pool);
    cudaGetSymbolAddress((void**)&p_cnt,   g_cnt);
    cudaGetSymbolAddress((void**)&p_whi,   g_whi);
    cudaGetSymbolAddress((void**)&p_wlo,   g_wlo);
    cudaGetSymbolAddress((void**)&p_deg,   g_deg);
    cudaGetSymbolAddress((void**)&p_off,   g_off);
    cudaGetSymbolAddress((void**)&p_cur,   g_cur);
    cudaGetSymbolAddress((void**)&p_elist, g_elist);
    cudaGetSymbolAddress((void**)&p_bsum,  g_bsum);

    static int smem_set = 0;
    if (!smem_set) {
        cudaFuncSetAttribute(gemm_dual,
                             cudaFuncAttributeMaxDynamicSharedMemorySize,
                             2 * STG_B);
        smem_set = 1;
    }

    const int gemm_grid = (nN + 63) / 64;
    const int row_grid  = (nN + 7) / 8;
    const int e_grid    = (nE + 255) / 256;
    const int nB        = (nN + SCAN_B - 1) / SCAN_B;

    wsplit<<<(6 * DD * DD + 255) / 256, 256>>>(W_self, W_msg, p_whi, p_wlo);
    zero_misc<<<(nN + 255) / 256, 256>>>(p_pool, p_cnt, p_deg, nN);
    csr_hist<<<e_grid, 256>>>(dst, p_deg, nE);
    csr_bsum<<<nB, SCAN_B>>>(p_deg, p_bsum, nN);
    csr_bscan<<<1, SCAN_B>>>(p_bsum, nB);
    csr_write<<<nB, SCAN_B>>>(p_deg, p_bsum, p_off, p_cur, nN, nE);
    csr_place<<<e_grid, 256>>>(src, dst, p_cur, p_elist, nE);

    for (int i = 0; i < 3; i++) {
        const float* xin = (i == 0) ? x : p_x;
        const float* wsH = p_whi + (size_t)i * DD * DD;
        const float* wsL = p_wlo + (size_t)i * DD * DD;
        const float* wmH = p_whi + (size_t)(3 + i) * DD * DD;
        const float* wmL = p_wlo + (size_t)(3 + i) * DD * DD;

        gemm_dual<<<gemm_grid, 256, 2 * STG_B>>>(xin, wsH, wsL, wmH, wmL,
                                                 b_self + i * DD, b_msg + i * DD,
                                                 p_acc, p_msg, nN);
        if (i < 2)
            gather_ln<<<row_grid, 256>>>(p_off, p_elist, p_msg, p_acc,
                                         ln_g + i * DD, ln_b + i * DD, p_x, nN);
        else
            gather_pool<<<row_grid, 256>>>(p_off, p_elist, p_msg, p_acc,
                                           batch, p_pool, p_cnt, nN);
    }

    head_kernel<<<GG, DD>>>(p_pool, p_cnt, W1, b1, W2, b2, (float*)d_out);
}

// round 10
// speedup vs baseline: 2.9170x; 1.2662x over previous
#include <cuda_runtime.h>
#include <cuda_bf16.h>
#include <math.h>
#include <stdint.h>

#define NN_MAX 50000
#define NE_MAX 1000000
#define DD 128
#define GG 64
#define CC 32
#define EPS 1e-5f
#define SCAN_B 256
#define NB_MAX ((NN_MAX + SCAN_B - 1) / SCAN_B)

// ---------------- scratch (no allocation allowed) ----------------
__device__ float g_acc[(size_t)NN_MAX * DD];   // self-linear result
__device__ float g_msg[(size_t)NN_MAX * DD];   // message-linear result
__device__ float g_x  [(size_t)NN_MAX * DD];   // activations between layers
__device__ float g_pool[GG * DD];
__device__ float g_cnt [GG];
// packed bf16 weights, MMA B-fragment layout: [mat][kk][n] u32 = (w[2kk+1][n]<<16)|w[2kk][n]
__device__ uint32_t g_wphi[6 * 64 * DD];
__device__ uint32_t g_wplo[6 * 64 * DD];
__device__ int   g_deg[NN_MAX];
__device__ int   g_off[NN_MAX + 1];
__device__ int   g_cur[NN_MAX];
__device__ int   g_elist[NE_MAX];
__device__ int   g_bsum[NB_MAX];

__device__ __forceinline__ void mma16(float* c, const uint32_t* a,
                                      uint32_t b0, uint32_t b1)
{
    asm volatile(
        "mma.sync.aligned.m16n8k16.row.col.f32.bf16.bf16.f32 "
        "{%0,%1,%2,%3},{%4,%5,%6,%7},{%8,%9},{%0,%1,%2,%3};"
        : "+f"(c[0]), "+f"(c[1]), "+f"(c[2]), "+f"(c[3])
        : "r"(a[0]), "r"(a[1]), "r"(a[2]), "r"(a[3]), "r"(b0), "r"(b1));
}

__device__ __forceinline__ uint32_t smem_u32(const void* p)
{
    uint32_t a;
    asm("{ .reg .u64 t; cvta.to.shared.u64 t, %1; cvt.u32.u64 %0, t; }"
        : "=r"(a) : "l"(p));
    return a;
}

__device__ __forceinline__ void cp16(uint32_t dst, const void* src, bool pred)
{
    int sz = pred ? 16 : 0;
    asm volatile("cp.async.cg.shared.global [%0], [%1], 16, %2;"
                 :: "r"(dst), "l"(src), "r"(sz));
}
#define CP_COMMIT() asm volatile("cp.async.commit_group;" ::: "memory")

// split (a,b) fp32 pair into packed bf16 hi and lo words
__device__ __forceinline__ void hilo2(float a, float b, uint32_t& hi, uint32_t& lo)
{
    __nv_bfloat16 ha = __float2bfloat16_rn(a), hb = __float2bfloat16_rn(b);
    __nv_bfloat16 la = __float2bfloat16_rn(a - __bfloat162float(ha));
    __nv_bfloat16 lb = __float2bfloat16_rn(b - __bfloat162float(hb));
    hi = ((uint32_t)__bfloat16_as_ushort(hb) << 16) | __bfloat16_as_ushort(ha);
    lo = ((uint32_t)__bfloat16_as_ushort(lb) << 16) | __bfloat16_as_ushort(la);
}

// ---------------- weight pack: W -> bf16 hi/lo in B-fragment layout ----------------
__global__ void wsplit_pack(const float* __restrict__ Wself,
                            const float* __restrict__ Wmsg,
                            uint32_t* __restrict__ phi,
                            uint32_t* __restrict__ plo)
{
    const int total = 6 * 64 * DD;
    int i = blockIdx.x * blockDim.x + threadIdx.x;
    if (i >= total) return;
    int mat = i / (64 * DD);
    int rem = i % (64 * DD);
    int kk = rem / DD, n = rem % DD;
    const float* Wsrc = (mat < 3) ? (Wself + (size_t)mat * DD * DD)
                                  : (Wmsg + (size_t)(mat - 3) * DD * DD);
    float w0 = Wsrc[(size_t)(2 * kk) * DD + n];
    float w1 = Wsrc[(size_t)(2 * kk + 1) * DD + n];
    hilo2(w0, w1, phi[i], plo[i]);
}

// ---------------- CSR build ----------------
__global__ void zero_misc(float* pool, float* cnt, int* deg, int nN)
{
    const int t = blockIdx.x * blockDim.x + threadIdx.x;
    if (t < GG * DD) pool[t] = 0.f;
    if (t < GG) cnt[t] = 0.f;
    if (t < nN) deg[t] = 0;
}

__global__ void csr_hist(const int* __restrict__ dst, int* __restrict__ deg,
                         int nE)
{
    int e = blockIdx.x * blockDim.x + threadIdx.x;
    if (e < nE) atomicAdd(&deg[dst[e]], 1);
}

__global__ void __launch_bounds__(SCAN_B) csr_bsum(const int* __restrict__ deg,
                                                   int* __restrict__ bsum, int nN)
{
    __shared__ int sm[SCAN_B];
    const int t = threadIdx.x;
    const int i = blockIdx.x * SCAN_B + t;
    sm[t] = (i < nN) ? deg[i] : 0;
    __syncthreads();
#pragma unroll
    for (int o = SCAN_B / 2; o; o >>= 1) {
        if (t < o) sm[t] += sm[t + o];
        __syncthreads();
    }
    if (t == 0) bsum[blockIdx.x] = sm[0];
}

__global__ void __launch_bounds__(SCAN_B) csr_bscan(int* __restrict__ bsum, int nB)
{
    __shared__ int wsum[8];
    const int t = threadIdx.x;
    const int lane = t & 31;
    const int w = t >> 5;
    int v = (t < nB) ? bsum[t] : 0;
    int x = v;
#pragma unroll
    for (int o = 1; o < 32; o <<= 1) {
        int y = __shfl_up_sync(0xffffffffu, x, o);
        if (lane >= o) x += y;
    }
    if (lane == 31) wsum[w] = x;
    __syncthreads();
    if (t < 8) {
        int s = wsum[t];
#pragma unroll
        for (int o = 1; o < 8; o <<= 1) {
            int y = __shfl_up_sync(0xffu, s, o);
            if (t >= o) s += y;
        }
        wsum[t] = s;
    }
    __syncthreads();
    int wo = (w == 0) ? 0 : wsum[w - 1];
    if (t < nB) bsum[t] = wo + x - v;   // exclusive
}

__global__ void __launch_bounds__(SCAN_B) csr_write(const int* __restrict__ deg,
                                                    const int* __restrict__ bsum,
                                                    int* __restrict__ off,
                                                    int* __restrict__ cur,
                                                    int nN, int nE)
{
    __shared__ int wsum[8];
    const int t = threadIdx.x;
    const int lane = t & 31;
    const int w = t >> 5;
    const int i = blockIdx.x * SCAN_B + t;
    int v = (i < nN) ? deg[i] : 0;
    int x = v;
#pragma unroll
    for (int o = 1; o < 32; o <<= 1) {
        int y = __shfl_up_sync(0xffffffffu, x, o);
        if (lane >= o) x += y;
    }
    if (lane == 31) wsum[w] = x;
    __syncthreads();
    if (t < 8) {
        int s = wsum[t];
#pragma unroll
        for (int o = 1; o < 8; o <<= 1) {
            int y = __shfl_up_sync(0xffu, s, o);
            if (t >= o) s += y;
        }
        wsum[t] = s;
    }
    __syncthreads();
    int wo = (w == 0) ? 0 : wsum[w - 1];
    int excl = bsum[blockIdx.x] + wo + x - v;
    if (i < nN) {
        off[i] = excl;
        cur[i] = excl;
    }
    if (i == nN - 1) off[nN] = nE;
}

__global__ void csr_place(const int* __restrict__ src,
                          const int* __restrict__ dst,
                          int* __restrict__ cur, int* __restrict__ elist, int nE)
{
    int e = blockIdx.x * blockDim.x + threadIdx.x;
    if (e < nE) {
        int p = atomicAdd(&cur[dst[e]], 1);
        elist[p] = src[e];
    }
}

// ---------------- fused dual GEMM v3: bf16 hi/lo m16n8k16 + cp.async 2-stage --
// CTA 64 rows; warp = {half(self/msg), rowslab(32), colhalf(64)}.
// stage: X fp32 [64][20] (5120B) + 4 packed W mats [8][136] u32 (4352B each)
#define XB2   5120
#define WMB   4352
#define STG   (XB2 + 4 * WMB)   // 22528

__global__ void __launch_bounds__(256) gemm_dual(const float* __restrict__ X,
                                                 const uint32_t* __restrict__ WsH,
                                                 const uint32_t* __restrict__ WsL,
                                                 const uint32_t* __restrict__ WmH,
                                                 const uint32_t* __restrict__ WmL,
                                                 const float* __restrict__ bS,
                                                 const float* __restrict__ bM,
                                                 float* __restrict__ Ys,
                                                 float* __restrict__ Ym, int nrows)
{
    extern __shared__ char smem[];
    const uint32_t sb = smem_u32(smem);

    const int tid  = threadIdx.x;
    const int lane = tid & 31;
    const int warp = tid >> 5;
    const int half = warp >> 2;          // 0: self, 1: msg
    const int rs   = (warp >> 1) & 1;    // row slab (32 rows)
    const int ch   = warp & 1;           // col half (64 cols)
    const int row0 = blockIdx.x * 64;
    const int gid  = lane >> 2;
    const int tig  = lane & 3;

    const uint32_t* Wmats[4];
    Wmats[0] = WsH; Wmats[1] = WsL; Wmats[2] = WmH; Wmats[3] = WmL;

    const int xr = tid >> 2;             // X staging: row
    const int xc = (tid & 3) * 4;        // X staging: col group
    const int wkk = tid >> 5;            // W staging: kk row (0..7)
    const int wn4 = (tid & 31) * 4;      // W staging: n group

    float c[2][8][4];
#pragma unroll
    for (int s = 0; s < 2; s++)
#pragma unroll
        for (int t = 0; t < 8; t++)
#pragma unroll
            for (int j = 0; j < 4; j++) c[s][t][j] = 0.f;

    // prologue: stage k-chunk 0
    {
        const int gr = row0 + xr;
        cp16(sb + xr * 80 + xc * 4, &X[(size_t)gr * DD + xc], gr < nrows);
#pragma unroll
        for (int m = 0; m < 4; m++)
            cp16(sb + XB2 + m * WMB + wkk * 544 + wn4 * 4,
                 &Wmats[m][(size_t)wkk * DD + wn4], true);
    }
    CP_COMMIT();

    for (int it = 0; it < 8; it++) {
        const int buf = it & 1;
        if (it < 7) {
            const int k0n = (it + 1) * 16;
            const int kkb = (it + 1) * 8;
            const uint32_t st = sb + (buf ^ 1) * STG;
            const int gr = row0 + xr;
            cp16(st + xr * 80 + xc * 4, &X[(size_t)gr * DD + k0n + xc], gr < nrows);
#pragma unroll
            for (int m = 0; m < 4; m++)
                cp16(st + XB2 + m * WMB + wkk * 544 + wn4 * 4,
                     &Wmats[m][(size_t)(kkb + wkk) * DD + wn4], true);
            CP_COMMIT();
            asm volatile("cp.async.wait_group 1;" ::: "memory");
        } else {
            asm volatile("cp.async.wait_group 0;" ::: "memory");
        }
        __syncthreads();

        const float* Xs = (const float*)(smem + buf * STG);
        const uint32_t* Bh = (const uint32_t*)(smem + buf * STG + XB2 + (half * 2) * WMB);
        const uint32_t* Bl = (const uint32_t*)(smem + buf * STG + XB2 + (half * 2 + 1) * WMB);

        // A fragments (m16k16) hi/lo, per row slab
        uint32_t ah[2][4], al[2][4];
#pragma unroll
        for (int s = 0; s < 2; s++) {
            const int rA = rs * 32 + s * 16 + gid;
            float2 x0 = *reinterpret_cast<const float2*>(&Xs[rA * 20 + 2 * tig]);
            float2 x1 = *reinterpret_cast<const float2*>(&Xs[(rA + 8) * 20 + 2 * tig]);
            float2 x2 = *reinterpret_cast<const float2*>(&Xs[rA * 20 + 2 * tig + 8]);
            float2 x3 = *reinterpret_cast<const float2*>(&Xs[(rA + 8) * 20 + 2 * tig + 8]);
            hilo2(x0.x, x0.y, ah[s][0], al[s][0]);
            hilo2(x1.x, x1.y, ah[s][1], al[s][1]);
            hilo2(x2.x, x2.y, ah[s][2], al[s][2]);
            hilo2(x3.x, x3.y, ah[s][3], al[s][3]);
        }

#pragma unroll
        for (int t = 0; t < 8; t++) {
            const int n = ch * 64 + t * 8 + gid;
            uint32_t bh0 = Bh[tig * 136 + n];
            uint32_t bh1 = Bh[(tig + 4) * 136 + n];
            uint32_t bl0 = Bl[tig * 136 + n];
            uint32_t bl1 = Bl[(tig + 4) * 136 + n];
#pragma unroll
            for (int s = 0; s < 2; s++) {
                mma16(c[s][t], ah[s], bh0, bh1);   // hi*hi
                mma16(c[s][t], ah[s], bl0, bl1);   // hi*lo
                mma16(c[s][t], al[s], bh0, bh1);   // lo*hi
            }
        }
        __syncthreads();
    }

    float* Y = half ? Ym : Ys;
    const float* bias = half ? bM : bS;
#pragma unroll
    for (int s = 0; s < 2; s++)
#pragma unroll
        for (int t = 0; t < 8; t++) {
            int col = ch * 64 + t * 8 + tig * 2;
            float2 b = *reinterpret_cast<const float2*>(&bias[col]);
            int r = row0 + rs * 32 + s * 16 + gid;
            if (r < nrows) {
                float2 o; o.x = c[s][t][0] + b.x; o.y = c[s][t][1] + b.y;
                *reinterpret_cast<float2*>(&Y[(size_t)r * DD + col]) = o;
            }
            int r2 = r + 8;
            if (r2 < nrows) {
                float2 o; o.x = c[s][t][2] + b.x; o.y = c[s][t][3] + b.y;
                *reinterpret_cast<float2*>(&Y[(size_t)r2 * DD + col]) = o;
            }
        }
}

// ---------------- gather (CSR) + ReLU + LayerNorm, warp per node ----------------
__global__ void __launch_bounds__(256) gather_ln(const int* __restrict__ off,
                                                 const int* __restrict__ elist,
                                                 const float* __restrict__ msg,
                                                 const float* __restrict__ selfv,
                                                 const float* __restrict__ lg,
                                                 const float* __restrict__ lb,
                                                 float* __restrict__ out, int nN)
{
    const int lane = threadIdx.x & 31;
    const int row  = (blockIdx.x * blockDim.x + threadIdx.x) >> 5;
    if (row >= nN) return;

    float4 a0 = *reinterpret_cast<const float4*>(&selfv[(size_t)row * DD + lane * 4]);
    float4 a1 = make_float4(0.f, 0.f, 0.f, 0.f);

    const int b = __ldg(&off[row]);
    const int e = __ldg(&off[row + 1]);
    int i = b;
    for (; i + 2 <= e; i += 2) {
        int s0 = __ldg(&elist[i]);
        int s1 = __ldg(&elist[i + 1]);
        float4 v0 = *reinterpret_cast<const float4*>(&msg[(size_t)s0 * DD + lane * 4]);
        float4 v1 = *reinterpret_cast<const float4*>(&msg[(size_t)s1 * DD + lane * 4]);
        a0.x += v0.x; a0.y += v0.y; a0.z += v0.z; a0.w += v0.w;
        a1.x += v1.x; a1.y += v1.y; a1.z += v1.z; a1.w += v1.w;
    }
    if (i < e) {
        int s0 = __ldg(&elist[i]);
        float4 v0 = *reinterpret_cast<const float4*>(&msg[(size_t)s0 * DD + lane * 4]);
        a0.x += v0.x; a0.y += v0.y; a0.z += v0.z; a0.w += v0.w;
    }
    float4 v;
    v.x = fmaxf(a0.x + a1.x, 0.f);
    v.y = fmaxf(a0.y + a1.y, 0.f);
    v.z = fmaxf(a0.z + a1.z, 0.f);
    v.w = fmaxf(a0.w + a1.w, 0.f);

    float s  = v.x + v.y + v.z + v.w;
    float ss = v.x * v.x + v.y * v.y + v.z * v.z + v.w * v.w;
#pragma unroll
    for (int o = 16; o; o >>= 1) {
        s  += __shfl_xor_sync(0xffffffffu, s,  o);
        ss += __shfl_xor_sync(0xffffffffu, ss, o);
    }
    const float mu  = s * (1.f / 128.f);
    const float var = ss * (1.f / 128.f) - mu * mu;
    const float inv = rsqrtf(var + EPS);

    const float4 gv = *reinterpret_cast<const float4*>(&lg[lane * 4]);
    const float4 bv = *reinterpret_cast<const float4*>(&lb[lane * 4]);
    float4 o4;
    o4.x = gv.x * (v.x - mu) * inv + bv.x;
    o4.y = gv.y * (v.y - mu) * inv + bv.y;
    o4.z = gv.z * (v.z - mu) * inv + bv.z;
    o4.w = gv.w * (v.w - mu) * inv + bv.w;
    *reinterpret_cast<float4*>(&out[(size_t)row * DD + lane * 4]) = o4;
}

// ---------------- gather (CSR) + ReLU + pool, warp per node ----------------
__global__ void __launch_bounds__(256) gather_pool(const int* __restrict__ off,
                                                   const int* __restrict__ elist,
                                                   const float* __restrict__ msg,
                                                   const float* __restrict__ selfv,
                                                   const int* __restrict__ batch,
                                                   float* __restrict__ pool,
                                                   float* __restrict__ cnt, int nN)
{
    const int lane = threadIdx.x & 31;
    const int row  = (blockIdx.x * blockDim.x + threadIdx.x) >> 5;
    if (row >= nN) return;

    float4 a0 = *reinterpret_cast<const float4*>(&selfv[(size_t)row * DD + lane * 4]);
    float4 a1 = make_float4(0.f, 0.f, 0.f, 0.f);

    const int b = __ldg(&off[row]);
    const int e = __ldg(&off[row + 1]);
    int i = b;
    for (; i + 2 <= e; i += 2) {
        int s0 = __ldg(&elist[i]);
        int s1 = __ldg(&elist[i + 1]);
        float4 v0 = *reinterpret_cast<const float4*>(&msg[(size_t)s0 * DD + lane * 4]);
        float4 v1 = *reinterpret_cast<const float4*>(&msg[(size_t)s1 * DD + lane * 4]);
        a0.x += v0.x; a0.y += v0.y; a0.z += v0.z; a0.w += v0.w;
        a1.x += v1.x; a1.y += v1.y; a1.z += v1.z; a1.w += v1.w;
    }
    if (i < e) {
        int s0 = __ldg(&elist[i]);
        float4 v0 = *reinterpret_cast<const float4*>(&msg[(size_t)s0 * DD + lane * 4]);
        a0.x += v0.x; a0.y += v0.y; a0.z += v0.z; a0.w += v0.w;
    }
    float4 v;
    v.x = fmaxf(a0.x + a1.x, 0.f);
    v.y = fmaxf(a0.y + a1.y, 0.f);
    v.z = fmaxf(a0.z + a1.z, 0.f);
    v.w = fmaxf(a0.w + a1.w, 0.f);

    const int g = __ldg(&batch[row]);
    float* p = &pool[(size_t)g * DD + lane * 4];
    asm volatile("red.global.add.v4.f32 [%0], {%1,%2,%3,%4};"
                 :: "l"(p), "f"(v.x), "f"(v.y), "f"(v.z), "f"(v.w) : "memory");
    if (lane == 0) atomicAdd(&cnt[g], 1.0f);
}

// ---------------- head: mean, 2 linears, log_softmax ----------------
__global__ void __launch_bounds__(DD) head_kernel(const float* __restrict__ pool,
                                                  const float* __restrict__ cnt,
                                                  const float* __restrict__ W1,
                                                  const float* __restrict__ b1,
                                                  const float* __restrict__ W2,
                                                  const float* __restrict__ b2,
                                                  float* __restrict__ out)
{
    __shared__ float p[DD];
    __shared__ float h[DD];
    const int g = blockIdx.x;
    const int t = threadIdx.x;

    const float c = fmaxf(cnt[g], 1.f);
    p[t] = pool[g * DD + t] / c;
    __syncthreads();

    float a = b1[t];
#pragma unroll 8
    for (int k = 0; k < DD; k++) a += p[k] * W1[k * DD + t];
    h[t] = a;
    __syncthreads();

    if (t < CC) {
        float l = b2[t];
#pragma unroll 8
        for (int d = 0; d < DD; d++) l += h[d] * W2[d * CC + t];

        float m = l;
#pragma unroll
        for (int o = 16; o; o >>= 1) m = fmaxf(m, __shfl_xor_sync(0xffffffffu, m, o));
        float e = expf(l - m);
        float s = e;
#pragma unroll
        for (int o = 16; o; o >>= 1) s += __shfl_xor_sync(0xffffffffu, s, o);
        out[g * CC + t] = l - m - logf(s);
    }
}

// ---------------- launch ----------------
extern "C" void kernel_launch(void* const* d_in, const int* in_sizes, int n_in,
                              void* d_out, int out_size)
{
    const float* x      = (const float*)d_in[0];
    const float* W_self = (const float*)d_in[1];
    const float* b_self = (const float*)d_in[2];
    const float* W_msg  = (const float*)d_in[3];
    const float* b_msg  = (const float*)d_in[4];
    const float* ln_g   = (const float*)d_in[5];
    const float* ln_b   = (const float*)d_in[6];
    const float* W1     = (const float*)d_in[7];
    const float* b1     = (const float*)d_in[8];
    const float* W2     = (const float*)d_in[9];
    const float* b2     = (const float*)d_in[10];
    const int*   eidx   = (const int*)d_in[11];
    const int*   batch  = (const int*)d_in[12];

    const int nN = in_sizes[0] / DD;
    const int nE = in_sizes[11] / 2;
    const int* src = eidx;
    const int* dst = eidx + nE;

    float *p_acc, *p_msg, *p_x, *p_pool, *p_cnt;
    uint32_t *p_phi, *p_plo;
    int *p_deg, *p_off, *p_cur, *p_elist, *p_bsum;
    cudaGetSymbolAddress((void**)&p_acc,   g_acc);
    cudaGetSymbolAddress((void**)&p_msg,   g_msg);
    cudaGetSymbolAddress((void**)&p_x,     g_x);
    cudaGetSymbolAddress((void**)&p_pool,  g_pool);
    cudaGetSymbolAddress((void**)&p_cnt,   g_cnt);
    cudaGetSymbolAddress((void**)&p_phi,   g_wphi);
    cudaGetSymbolAddress((void**)&p_plo,   g_wplo);
    cudaGetSymbolAddress((void**)&p_deg,   g_deg);
    cudaGetSymbolAddress((void**)&p_off,   g_off);
    cudaGetSymbolAddress((void**)&p_cur,   g_cur);
    cudaGetSymbolAddress((void**)&p_elist, g_elist);
    cudaGetSymbolAddress((void**)&p_bsum,  g_bsum);

    const int gemm_grid = (nN + 63) / 64;
    const int row_grid  = (nN + 7) / 8;
    const int e_grid    = (nE + 255) / 256;
    const int nB        = (nN + SCAN_B - 1) / SCAN_B;

    wsplit_pack<<<(6 * 64 * DD + 255) / 256, 256>>>(W_self, W_msg, p_phi, p_plo);
    zero_misc<<<(nN + 255) / 256, 256>>>(p_pool, p_cnt, p_deg, nN);
    csr_hist<<<e_grid, 256>>>(dst, p_deg, nE);
    csr_bsum<<<nB, SCAN_B>>>(p_deg, p_bsum, nN);
    csr_bscan<<<1, SCAN_B>>>(p_bsum, nB);
    csr_write<<<nB, SCAN_B>>>(p_deg, p_bsum, p_off, p_cur, nN, nE);
    csr_place<<<e_grid, 256>>>(src, dst, p_cur, p_elist, nE);

    for (int i = 0; i < 3; i++) {
        const float* xin = (i == 0) ? x : p_x;
        const uint32_t* wsH = p_phi + (size_t)i * 64 * DD;
        const uint32_t* wsL = p_plo + (size_t)i * 64 * DD;
        const uint32_t* wmH = p_phi + (size_t)(3 + i) * 64 * DD;
        const uint32_t* wmL = p_plo + (size_t)(3 + i) * 64 * DD;

        gemm_dual<<<gemm_grid, 256, 2 * STG>>>(xin, wsH, wsL, wmH, wmL,
                                               b_self + i * DD, b_msg + i * DD,
                                               p_acc, p_msg, nN);
        if (i < 2)
            gather_ln<<<row_grid, 256>>>(p_off, p_elist, p_msg, p_acc,
                                         ln_g + i * DD, ln_b + i * DD, p_x, nN);
        else
            gather_pool<<<row_grid, 256>>>(p_off, p_elist, p_msg, p_acc,
                                           batch, p_pool, p_cnt, nN);
    }

    head_kernel<<<GG, DD>>>(p_pool, p_cnt, W1, b1, W2, b2, (float*)d_out);
}

// round 11
// speedup vs baseline: 3.0374x; 1.0413x over previous
#include <cuda_runtime.h>
#include <cuda_bf16.h>
#include <math.h>
#include <stdint.h>

#define NN_MAX 50000
#define NE_MAX 1000000
#define DD 128
#define GG 64
#define CC 32
#define EPS 1e-5f
#define SCAN_B 256
#define NB_MAX ((NN_MAX + SCAN_B - 1) / SCAN_B)

// ---------------- scratch (no allocation allowed) ----------------
__device__ float g_acc[(size_t)NN_MAX * DD];
__device__ float g_msg[(size_t)NN_MAX * DD];
__device__ float g_x  [(size_t)NN_MAX * DD];
__device__ float g_pool[GG * DD];
__device__ float g_cnt [GG];
// packed bf16 weights, MMA B-fragment layout: [mat][kk][n] u32 = (w[2kk+1][n]<<16)|w[2kk][n]
__device__ uint32_t g_wphi[6 * 64 * DD];
__device__ uint32_t g_wplo[6 * 64 * DD];
__device__ int   g_deg[NN_MAX];
__device__ int   g_off[NN_MAX + 1];
__device__ int   g_cur[NN_MAX];
__device__ int   g_elist[NE_MAX];
__device__ int   g_bsum[NB_MAX];

__device__ __forceinline__ void mma16(float* c, const uint32_t* a,
                                      uint32_t b0, uint32_t b1)
{
    asm volatile(
        "mma.sync.aligned.m16n8k16.row.col.f32.bf16.bf16.f32 "
        "{%0,%1,%2,%3},{%4,%5,%6,%7},{%8,%9},{%0,%1,%2,%3};"
        : "+f"(c[0]), "+f"(c[1]), "+f"(c[2]), "+f"(c[3])
        : "r"(a[0]), "r"(a[1]), "r"(a[2]), "r"(a[3]), "r"(b0), "r"(b1));
}

__device__ __forceinline__ uint32_t smem_u32(const void* p)
{
    uint32_t a;
    asm("{ .reg .u64 t; cvta.to.shared.u64 t, %1; cvt.u32.u64 %0, t; }"
        : "=r"(a) : "l"(p));
    return a;
}

__device__ __forceinline__ void cp16(uint32_t dst, const void* src, bool pred)
{
    int sz = pred ? 16 : 0;
    asm volatile("cp.async.cg.shared.global [%0], [%1], 16, %2;"
                 :: "r"(dst), "l"(src), "r"(sz));
}
#define CP_COMMIT() asm volatile("cp.async.commit_group;" ::: "memory")

__device__ __forceinline__ void hilo2(float a, float b, uint32_t& hi, uint32_t& lo)
{
    __nv_bfloat16 ha = __float2bfloat16_rn(a), hb = __float2bfloat16_rn(b);
    __nv_bfloat16 la = __float2bfloat16_rn(a - __bfloat162float(ha));
    __nv_bfloat16 lb = __float2bfloat16_rn(b - __bfloat162float(hb));
    hi = ((uint32_t)__bfloat16_as_ushort(hb) << 16) | __bfloat16_as_ushort(ha);
    lo = ((uint32_t)__bfloat16_as_ushort(lb) << 16) | __bfloat16_as_ushort(la);
}

// ---------------- weight pack ----------------
__global__ void wsplit_pack(const float* __restrict__ Wself,
                            const float* __restrict__ Wmsg,
                            uint32_t* __restrict__ phi,
                            uint32_t* __restrict__ plo)
{
    const int total = 6 * 64 * DD;
    int i = blockIdx.x * blockDim.x + threadIdx.x;
    if (i >= total) return;
    int mat = i / (64 * DD);
    int rem = i % (64 * DD);
    int kk = rem / DD, n = rem % DD;
    const float* Wsrc = (mat < 3) ? (Wself + (size_t)mat * DD * DD)
                                  : (Wmsg + (size_t)(mat - 3) * DD * DD);
    float w0 = Wsrc[(size_t)(2 * kk) * DD + n];
    float w1 = Wsrc[(size_t)(2 * kk + 1) * DD + n];
    hilo2(w0, w1, phi[i], plo[i]);
}

// ---------------- CSR build ----------------
__global__ void zero_misc(float* pool, float* cnt, int* deg, int nN)
{
    const int t = blockIdx.x * blockDim.x + threadIdx.x;
    if (t < GG * DD) pool[t] = 0.f;
    if (t < GG) cnt[t] = 0.f;
    if (t < nN) deg[t] = 0;
}

__global__ void csr_hist(const int* __restrict__ dst, int* __restrict__ deg,
                         int nE)
{
    int e = blockIdx.x * blockDim.x + threadIdx.x;
    if (e < nE) atomicAdd(&deg[dst[e]], 1);
}

__global__ void __launch_bounds__(SCAN_B) csr_bsum(const int* __restrict__ deg,
                                                   int* __restrict__ bsum, int nN)
{
    __shared__ int sm[SCAN_B];
    const int t = threadIdx.x;
    const int i = blockIdx.x * SCAN_B + t;
    sm[t] = (i < nN) ? deg[i] : 0;
    __syncthreads();
#pragma unroll
    for (int o = SCAN_B / 2; o; o >>= 1) {
        if (t < o) sm[t] += sm[t + o];
        __syncthreads();
    }
    if (t == 0) bsum[blockIdx.x] = sm[0];
}

__global__ void __launch_bounds__(SCAN_B) csr_bscan(int* __restrict__ bsum, int nB)
{
    __shared__ int wsum[8];
    const int t = threadIdx.x;
    const int lane = t & 31;
    const int w = t >> 5;
    int v = (t < nB) ? bsum[t] : 0;
    int x = v;
#pragma unroll
    for (int o = 1; o < 32; o <<= 1) {
        int y = __shfl_up_sync(0xffffffffu, x, o);
        if (lane >= o) x += y;
    }
    if (lane == 31) wsum[w] = x;
    __syncthreads();
    if (t < 8) {
        int s = wsum[t];
#pragma unroll
        for (int o = 1; o < 8; o <<= 1) {
            int y = __shfl_up_sync(0xffu, s, o);
            if (t >= o) s += y;
        }
        wsum[t] = s;
    }
    __syncthreads();
    int wo = (w == 0) ? 0 : wsum[w - 1];
    if (t < nB) bsum[t] = wo + x - v;
}

__global__ void __launch_bounds__(SCAN_B) csr_write(const int* __restrict__ deg,
                                                    const int* __restrict__ bsum,
                                                    int* __restrict__ off,
                                                    int* __restrict__ cur,
                                                    int nN, int nE)
{
    __shared__ int wsum[8];
    const int t = threadIdx.x;
    const int lane = t & 31;
    const int w = t >> 5;
    const int i = blockIdx.x * SCAN_B + t;
    int v = (i < nN) ? deg[i] : 0;
    int x = v;
#pragma unroll
    for (int o = 1; o < 32; o <<= 1) {
        int y = __shfl_up_sync(0xffffffffu, x, o);
        if (lane >= o) x += y;
    }
    if (lane == 31) wsum[w] = x;
    __syncthreads();
    if (t < 8) {
        int s = wsum[t];
#pragma unroll
        for (int o = 1; o < 8; o <<= 1) {
            int y = __shfl_up_sync(0xffu, s, o);
            if (t >= o) s += y;
        }
        wsum[t] = s;
    }
    __syncthreads();
    int wo = (w == 0) ? 0 : wsum[w - 1];
    int excl = bsum[blockIdx.x] + wo + x - v;
    if (i < nN) {
        off[i] = excl;
        cur[i] = excl;
    }
    if (i == nN - 1) off[nN] = nE;
}

__global__ void csr_place(const int* __restrict__ src,
                          const int* __restrict__ dst,
                          int* __restrict__ cur, int* __restrict__ elist, int nE)
{
    int e = blockIdx.x * blockDim.x + threadIdx.x;
    if (e < nE) {
        int p = atomicAdd(&cur[dst[e]], 1);
        elist[p] = src[e];
    }
}

// ---------------- fused dual GEMM v4: bf16 hi/lo + 3-stage cp.async ----------
#define XB2   5120
#define WMB   4352
#define STG   (XB2 + 4 * WMB)   // 22528
#define NSTG  3

__global__ void __launch_bounds__(256) gemm_dual(const float* __restrict__ X,
                                                 const uint32_t* __restrict__ WsH,
                                                 const uint32_t* __restrict__ WsL,
                                                 const uint32_t* __restrict__ WmH,
                                                 const uint32_t* __restrict__ WmL,
                                                 const float* __restrict__ bS,
                                                 const float* __restrict__ bM,
                                                 float* __restrict__ Ys,
                                                 float* __restrict__ Ym, int nrows)
{
    extern __shared__ char smem[];
    const uint32_t sb = smem_u32(smem);

    const int tid  = threadIdx.x;
    const int lane = tid & 31;
    const int warp = tid >> 5;
    const int half = warp >> 2;
    const int rs   = (warp >> 1) & 1;
    const int ch   = warp & 1;
    const int row0 = blockIdx.x * 64;
    const int gid  = lane >> 2;
    const int tig  = lane & 3;

    const uint32_t* Wmats[4];
    Wmats[0] = WsH; Wmats[1] = WsL; Wmats[2] = WmH; Wmats[3] = WmL;

    const int xr = tid >> 2;
    const int xc = (tid & 3) * 4;
    const int wkk = tid >> 5;
    const int wn4 = (tid & 31) * 4;
    const int gr = row0 + xr;
    const bool xp = gr < nrows;

    float c[2][8][4];
#pragma unroll
    for (int s = 0; s < 2; s++)
#pragma unroll
        for (int t = 0; t < 8; t++)
#pragma unroll
            for (int j = 0; j < 4; j++) c[s][t][j] = 0.f;

    auto stage = [&](int chunk, uint32_t st) {
        cp16(st + xr * 80 + xc * 4, &X[(size_t)gr * DD + chunk * 16 + xc], xp);
#pragma unroll
        for (int m = 0; m < 4; m++)
            cp16(st + XB2 + m * WMB + wkk * 544 + wn4 * 4,
                 &Wmats[m][(size_t)(chunk * 8 + wkk) * DD + wn4], true);
    };

    stage(0, sb);           CP_COMMIT();
    stage(1, sb + STG);     CP_COMMIT();

#pragma unroll
    for (int it = 0; it < 8; it++) {
        const int buf = it % NSTG;
        if (it < 6) {
            stage(it + 2, sb + ((it + 2) % NSTG) * STG);
            CP_COMMIT();
            asm volatile("cp.async.wait_group 2;" ::: "memory");
        } else if (it == 6) {
            asm volatile("cp.async.wait_group 1;" ::: "memory");
        } else {
            asm volatile("cp.async.wait_group 0;" ::: "memory");
        }
        __syncthreads();

        const float* Xs = (const float*)(smem + buf * STG);
        const uint32_t* Bh = (const uint32_t*)(smem + buf * STG + XB2 + (half * 2) * WMB);
        const uint32_t* Bl = (const uint32_t*)(smem + buf * STG + XB2 + (half * 2 + 1) * WMB);

        uint32_t ah[2][4], al[2][4];
#pragma unroll
        for (int s = 0; s < 2; s++) {
            const int rA = rs * 32 + s * 16 + gid;
            float2 x0 = *reinterpret_cast<const float2*>(&Xs[rA * 20 + 2 * tig]);
            float2 x1 = *reinterpret_cast<const float2*>(&Xs[(rA + 8) * 20 + 2 * tig]);
            float2 x2 = *reinterpret_cast<const float2*>(&Xs[rA * 20 + 2 * tig + 8]);
            float2 x3 = *reinterpret_cast<const float2*>(&Xs[(rA + 8) * 20 + 2 * tig + 8]);
            hilo2(x0.x, x0.y, ah[s][0], al[s][0]);
            hilo2(x1.x, x1.y, ah[s][1], al[s][1]);
            hilo2(x2.x, x2.y, ah[s][2], al[s][2]);
            hilo2(x3.x, x3.y, ah[s][3], al[s][3]);
        }

#pragma unroll
        for (int t = 0; t < 8; t++) {
            const int n = ch * 64 + t * 8 + gid;
            uint32_t bh0 = Bh[tig * 136 + n];
            uint32_t bh1 = Bh[(tig + 4) * 136 + n];
            uint32_t bl0 = Bl[tig * 136 + n];
            uint32_t bl1 = Bl[(tig + 4) * 136 + n];
#pragma unroll
            for (int s = 0; s < 2; s++) {
                mma16(c[s][t], ah[s], bh0, bh1);
                mma16(c[s][t], ah[s], bl0, bl1);
                mma16(c[s][t], al[s], bh0, bh1);
            }
        }
        __syncthreads();
    }

    float* Y = half ? Ym : Ys;
    const float* bias = half ? bM : bS;
#pragma unroll
    for (int s = 0; s < 2; s++)
#pragma unroll
        for (int t = 0; t < 8; t++) {
            int col = ch * 64 + t * 8 + tig * 2;
            float2 b = *reinterpret_cast<const float2*>(&bias[col]);
            int r = row0 + rs * 32 + s * 16 + gid;
            if (r < nrows) {
                float2 o; o.x = c[s][t][0] + b.x; o.y = c[s][t][1] + b.y;
                *reinterpret_cast<float2*>(&Y[(size_t)r * DD + col]) = o;
            }
            int r2 = r + 8;
            if (r2 < nrows) {
                float2 o; o.x = c[s][t][2] + b.x; o.y = c[s][t][3] + b.y;
                *reinterpret_cast<float2*>(&Y[(size_t)r2 * DD + col]) = o;
            }
        }
}

// ---------------- gather (CSR) + ReLU + LayerNorm ----------------
__global__ void __launch_bounds__(256) gather_ln(const int* __restrict__ off,
                                                 const int* __restrict__ elist,
                                                 const float* __restrict__ msg,
                                                 const float* __restrict__ selfv,
                                                 const float* __restrict__ lg,
                                                 const float* __restrict__ lb,
                                                 float* __restrict__ out, int nN)
{
    const int lane = threadIdx.x & 31;
    const int row  = (blockIdx.x * blockDim.x + threadIdx.x) >> 5;
    if (row >= nN) return;

    float4 a0 = *reinterpret_cast<const float4*>(&selfv[(size_t)row * DD + lane * 4]);
    float4 a1 = make_float4(0.f, 0.f, 0.f, 0.f);

    const int b = __ldg(&off[row]);
    const int e = __ldg(&off[row + 1]);
    int i = b;
    for (; i + 2 <= e; i += 2) {
        int s0 = __ldg(&elist[i]);
        int s1 = __ldg(&elist[i + 1]);
        float4 v0 = *reinterpret_cast<const float4*>(&msg[(size_t)s0 * DD + lane * 4]);
        float4 v1 = *reinterpret_cast<const float4*>(&msg[(size_t)s1 * DD + lane * 4]);
        a0.x += v0.x; a0.y += v0.y; a0.z += v0.z; a0.w += v0.w;
        a1.x += v1.x; a1.y += v1.y; a1.z += v1.z; a1.w += v1.w;
    }
    if (i < e) {
        int s0 = __ldg(&elist[i]);
        float4 v0 = *reinterpret_cast<const float4*>(&msg[(size_t)s0 * DD + lane * 4]);
        a0.x += v0.x; a0.y += v0.y; a0.z += v0.z; a0.w += v0.w;
    }
    float4 v;
    v.x = fmaxf(a0.x + a1.x, 0.f);
    v.y = fmaxf(a0.y + a1.y, 0.f);
    v.z = fmaxf(a0.z + a1.z, 0.f);
    v.w = fmaxf(a0.w + a1.w, 0.f);

    float s  = v.x + v.y + v.z + v.w;
    float ss = v.x * v.x + v.y * v.y + v.z * v.z + v.w * v.w;
#pragma unroll
    for (int o = 16; o; o >>= 1) {
        s  += __shfl_xor_sync(0xffffffffu, s,  o);
        ss += __shfl_xor_sync(0xffffffffu, ss, o);
    }
    const float mu  = s * (1.f / 128.f);
    const float var = ss * (1.f / 128.f) - mu * mu;
    const float inv = rsqrtf(var + EPS);

    const float4 gv = *reinterpret_cast<const float4*>(&lg[lane * 4]);
    const float4 bv = *reinterpret_cast<const float4*>(&lb[lane * 4]);
    float4 o4;
    o4.x = gv.x * (v.x - mu) * inv + bv.x;
    o4.y = gv.y * (v.y - mu) * inv + bv.y;
    o4.z = gv.z * (v.z - mu) * inv + bv.z;
    o4.w = gv.w * (v.w - mu) * inv + bv.w;
    *reinterpret_cast<float4*>(&out[(size_t)row * DD + lane * 4]) = o4;
}

// ---------------- gather (CSR) + ReLU + pool ----------------
__global__ void __launch_bounds__(256) gather_pool(const int* __restrict__ off,
                                                   const int* __restrict__ elist,
                                                   const float* __restrict__ msg,
                                                   const float* __restrict__ selfv,
                                                   const int* __restrict__ batch,
                                                   float* __restrict__ pool,
                                                   float* __restrict__ cnt, int nN)
{
    const int lane = threadIdx.x & 31;
    const int row  = (blockIdx.x * blockDim.x + threadIdx.x) >> 5;
    if (row >= nN) return;

    float4 a0 = *reinterpret_cast<const float4*>(&selfv[(size_t)row * DD + lane * 4]);
    float4 a1 = make_float4(0.f, 0.f, 0.f, 0.f);

    const int b = __ldg(&off[row]);
    const int e = __ldg(&off[row + 1]);
    int i = b;
    for (; i + 2 <= e; i += 2) {
        int s0 = __ldg(&elist[i]);
        int s1 = __ldg(&elist[i + 1]);
        float4 v0 = *reinterpret_cast<const float4*>(&msg[(size_t)s0 * DD + lane * 4]);
        float4 v1 = *reinterpret_cast<const float4*>(&msg[(size_t)s1 * DD + lane * 4]);
        a0.x += v0.x; a0.y += v0.y; a0.z += v0.z; a0.w += v0.w;
        a1.x += v1.x; a1.y += v1.y; a1.z += v1.z; a1.w += v1.w;
    }
    if (i < e) {
        int s0 = __ldg(&elist[i]);
        float4 v0 = *reinterpret_cast<const float4*>(&msg[(size_t)s0 * DD + lane * 4]);
        a0.x += v0.x; a0.y += v0.y; a0.z += v0.z; a0.w += v0.w;
    }
    float4 v;
    v.x = fmaxf(a0.x + a1.x, 0.f);
    v.y = fmaxf(a0.y + a1.y, 0.f);
    v.z = fmaxf(a0.z + a1.z, 0.f);
    v.w = fmaxf(a0.w + a1.w, 0.f);

    const int g = __ldg(&batch[row]);
    float* p = &pool[(size_t)g * DD + lane * 4];
    asm volatile("red.global.add.v4.f32 [%0], {%1,%2,%3,%4};"
                 :: "l"(p), "f"(v.x), "f"(v.y), "f"(v.z), "f"(v.w) : "memory");
    if (lane == 0) atomicAdd(&cnt[g], 1.0f);
}

// ---------------- head ----------------
__global__ void __launch_bounds__(DD) head_kernel(const float* __restrict__ pool,
                                                  const float* __restrict__ cnt,
                                                  const float* __restrict__ W1,
                                                  const float* __restrict__ b1,
                                                  const float* __restrict__ W2,
                                                  const float* __restrict__ b2,
                                                  float* __restrict__ out)
{
    __shared__ float p[DD];
    __shared__ float h[DD];
    const int g = blockIdx.x;
    const int t = threadIdx.x;

    const float c = fmaxf(cnt[g], 1.f);
    p[t] = pool[g * DD + t] / c;
    __syncthreads();

    float a = b1[t];
#pragma unroll 8
    for (int k = 0; k < DD; k++) a += p[k] * W1[k * DD + t];
    h[t] = a;
    __syncthreads();

    if (t < CC) {
        float l = b2[t];
#pragma unroll 8
        for (int d = 0; d < DD; d++) l += h[d] * W2[d * CC + t];

        float m = l;
#pragma unroll
        for (int o = 16; o; o >>= 1) m = fmaxf(m, __shfl_xor_sync(0xffffffffu, m, o));
        float e = expf(l - m);
        float s = e;
#pragma unroll
        for (int o = 16; o; o >>= 1) s += __shfl_xor_sync(0xffffffffu, s, o);
        out[g * CC + t] = l - m - logf(s);
    }
}

// ---------------- launch ----------------
extern "C" void kernel_launch(void* const* d_in, const int* in_sizes, int n_in,
                              void* d_out, int out_size)
{
    const float* x      = (const float*)d_in[0];
    const float* W_self = (const float*)d_in[1];
    const float* b_self = (const float*)d_in[2];
    const float* W_msg  = (const float*)d_in[3];
    const float* b_msg  = (const float*)d_in[4];
    const float* ln_g   = (const float*)d_in[5];
    const float* ln_b   = (const float*)d_in[6];
    const float* W1     = (const float*)d_in[7];
    const float* b1     = (const float*)d_in[8];
    const float* W2     = (const float*)d_in[9];
    const float* b2     = (const float*)d_in[10];
    const int*   eidx   = (const int*)d_in[11];
    const int*   batch  = (const int*)d_in[12];

    const int nN = in_sizes[0] / DD;
    const int nE = in_sizes[11] / 2;
    const int* src = eidx;
    const int* dst = eidx + nE;

    float *p_acc, *p_msg, *p_x, *p_pool, *p_cnt;
    uint32_t *p_phi, *p_plo;
    int *p_deg, *p_off, *p_cur, *p_elist, *p_bsum;
    cudaGetSymbolAddress((void**)&p_acc,   g_acc);
    cudaGetSymbolAddress((void**)&p_msg,   g_msg);
    cudaGetSymbolAddress((void**)&p_x,     g_x);
    cudaGetSymbolAddress((void**)&p_pool,  g_pool);
    cudaGetSymbolAddress((void**)&p_cnt,   g_cnt);
    cudaGetSymbolAddress((void**)&p_phi,   g_wphi);
    cudaGetSymbolAddress((void**)&p_plo,   g_wplo);
    cudaGetSymbolAddress((void**)&p_deg,   g_deg);
    cudaGetSymbolAddress((void**)&p_off,   g_off);
    cudaGetSymbolAddress((void**)&p_cur,   g_cur);
    cudaGetSymbolAddress((void**)&p_elist, g_elist);
    cudaGetSymbolAddress((void**)&p_bsum,  g_bsum);

    static cudaStream_t s2 = 0;
    static cudaEvent_t evFork = 0, evJoin = 0;
    static int init = 0;
    if (!init) {
        cudaFuncSetAttribute(gemm_dual,
                             cudaFuncAttributeMaxDynamicSharedMemorySize,
                             NSTG * STG);
        cudaStreamCreateWithFlags(&s2, cudaStreamNonBlocking);
        cudaEventCreateWithFlags(&evFork, cudaEventDisableTiming);
        cudaEventCreateWithFlags(&evJoin, cudaEventDisableTiming);
        init = 1;
    }

    const int gemm_grid = (nN + 63) / 64;
    const int row_grid  = (nN + 7) / 8;
    const int e_grid    = (nE + 255) / 256;
    const int nB        = (nN + SCAN_B - 1) / SCAN_B;

    // stream 0: weight pack (needed by layer-0 GEMM)
    wsplit_pack<<<(6 * 64 * DD + 255) / 256, 256>>>(W_self, W_msg, p_phi, p_plo);
    cudaEventRecord(evFork, 0);

    // stream s2: CSR build chain (independent of GEMM; needed by first gather)
    cudaStreamWaitEvent(s2, evFork, 0);
    zero_misc<<<(nN + 255) / 256, 256, 0, s2>>>(p_pool, p_cnt, p_deg, nN);
    csr_hist<<<e_grid, 256, 0, s2>>>(dst, p_deg, nE);
    csr_bsum<<<nB, SCAN_B, 0, s2>>>(p_deg, p_bsum, nN);
    csr_bscan<<<1, SCAN_B, 0, s2>>>(p_bsum, nB);
    csr_write<<<nB, SCAN_B, 0, s2>>>(p_deg, p_bsum, p_off, p_cur, nN, nE);
    csr_place<<<e_grid, 256, 0, s2>>>(src, dst, p_cur, p_elist, nE);
    cudaEventRecord(evJoin, s2);

    for (int i = 0; i < 3; i++) {
        const float* xin = (i == 0) ? x : p_x;
        const uint32_t* wsH = p_phi + (size_t)i * 64 * DD;
        const uint32_t* wsL = p_plo + (size_t)i * 64 * DD;
        const uint32_t* wmH = p_phi + (size_t)(3 + i) * 64 * DD;
        const uint32_t* wmL = p_plo + (size_t)(3 + i) * 64 * DD;

        gemm_dual<<<gemm_grid, 256, NSTG * STG>>>(xin, wsH, wsL, wmH, wmL,
                                                  b_self + i * DD, b_msg + i * DD,
                                                  p_acc, p_msg, nN);
        if (i == 0)
            cudaStreamWaitEvent(0, evJoin, 0);   // CSR ready before first gather
        if (i < 2)
            gather_ln<<<row_grid, 256>>>(p_off, p_elist, p_msg, p_acc,
                                         ln_g + i * DD, ln_b + i * DD, p_x, nN);
        else
            gather_pool<<<row_grid, 256>>>(p_off, p_elist, p_msg, p_acc,
                                           batch, p_pool, p_cnt, nN);
    }

    head_kernel<<<GG, DD>>>(p_pool, p_cnt, W1, b1, W2, b2, (float*)d_out);
}